// round 1
// baseline (speedup 1.0000x reference)
#include <cuda_runtime.h>
#include <math.h>

// ---------------- problem constants ----------------
#define BB   8
#define SSQ  1024
#define HIDD 1024
#define NH   8
#define HDD  128
#define MDD  8
#define NL   3
#define EPSS 1e-7f
#define INV_SQRT_D 0.08838834764831845f   // 1/sqrt(128)

// ---------------- scratch (device globals; no cudaMalloc allowed) ----------------
__device__ float g_cur   [BB * SSQ * HIDD];          // 32 MB
__device__ float g_qkv   [BB * SSQ * 3 * HIDD];      // 100 MB
__device__ float g_scores[BB * NH * SSQ * SSQ];      // 256 MB
__device__ float g_o     [BB * SSQ * HIDD];          // 32 MB
__device__ float g_qs    [BB * NH * SSQ];
__device__ float g_ks    [BB * NH * SSQ];

// ---------------- copy x -> g_cur ----------------
__global__ void k_copy4(const float4* __restrict__ src, float4* __restrict__ dst, int n4) {
    int i = blockIdx.x * blockDim.x + threadIdx.x;
    if (i < n4) dst[i] = src[i];
}

// ---------------- generic SGEMM: C[M,N] = A[M,K] * W[K,N] + bias[N] ----------------
// BM=128, BN=128, BK=16, 256 threads, 8x8 per thread. M,N,K multiples of tile dims.
__global__ __launch_bounds__(256) void k_sgemm_bias(
    const float* __restrict__ A, const float* __restrict__ W,
    const float* __restrict__ bias, float* __restrict__ C,
    int M, int N, int K)
{
    __shared__ float As[16][128];   // transposed: As[k][m]
    __shared__ float Bs[16][128];   // Bs[k][n]

    const int tid = threadIdx.x;
    const int tx = tid & 15, ty = tid >> 4;
    const int r0 = blockIdx.y * 128;
    const int c0 = blockIdx.x * 128;

    float acc[8][8];
#pragma unroll
    for (int i = 0; i < 8; i++)
#pragma unroll
        for (int j = 0; j < 8; j++) acc[i][j] = 0.f;

    for (int k0 = 0; k0 < K; k0 += 16) {
        // load A tile 128x16 (512 float4s, 2 per thread), scatter transposed
#pragma unroll
        for (int t = 0; t < 2; t++) {
            int f = tid + t * 256;
            int row = f >> 2, col4 = f & 3;
            float4 a4 = *(const float4*)&A[(size_t)(r0 + row) * K + k0 + col4 * 4];
            As[col4 * 4 + 0][row] = a4.x;
            As[col4 * 4 + 1][row] = a4.y;
            As[col4 * 4 + 2][row] = a4.z;
            As[col4 * 4 + 3][row] = a4.w;
        }
        // load B tile 16x128 (512 float4s, 2 per thread), direct
#pragma unroll
        for (int t = 0; t < 2; t++) {
            int f = tid + t * 256;
            int row = f >> 5, col4 = f & 31;
            float4 b4 = *(const float4*)&W[(size_t)(k0 + row) * N + c0 + col4 * 4];
            *(float4*)&Bs[row][col4 * 4] = b4;
        }
        __syncthreads();

#pragma unroll
        for (int k = 0; k < 16; k++) {
            float ra[8], rb[8];
            *(float4*)(ra)     = *(float4*)&As[k][ty * 8];
            *(float4*)(ra + 4) = *(float4*)&As[k][ty * 8 + 4];
            *(float4*)(rb)     = *(float4*)&Bs[k][tx * 8];
            *(float4*)(rb + 4) = *(float4*)&Bs[k][tx * 8 + 4];
#pragma unroll
            for (int i = 0; i < 8; i++)
#pragma unroll
                for (int j = 0; j < 8; j++) acc[i][j] = fmaf(ra[i], rb[j], acc[i][j]);
        }
        __syncthreads();
    }

    float4 bl = *(const float4*)&bias[c0 + tx * 8];
    float4 bh = *(const float4*)&bias[c0 + tx * 8 + 4];
#pragma unroll
    for (int i = 0; i < 8; i++) {
        size_t off = (size_t)(r0 + ty * 8 + i) * N + c0 + tx * 8;
        float4 o1 = make_float4(acc[i][0] + bl.x, acc[i][1] + bl.y, acc[i][2] + bl.z, acc[i][3] + bl.w);
        float4 o2 = make_float4(acc[i][4] + bh.x, acc[i][5] + bh.y, acc[i][6] + bh.z, acc[i][7] + bh.w);
        *(float4*)&C[off]     = o1;
        *(float4*)&C[off + 4] = o2;
    }
}

// ---------------- expmap0 row scales: tanh(||v||)/||v|| for q and k ----------------
__global__ void k_scales(const float* __restrict__ qkv, float* __restrict__ qs, float* __restrict__ ks) {
    int gw = (blockIdx.x * blockDim.x + threadIdx.x) >> 5;  // one warp per (b,h,s)
    int lane = threadIdx.x & 31;
    if (gw >= BB * NH * SSQ) return;
    int s = gw & (SSQ - 1);
    int bh = gw >> 10;
    int b = bh >> 3, h = bh & 7;
    const float* q = qkv + (size_t)(b * SSQ + s) * (3 * HIDD) + h * HDD;
    const float* k = q + HIDD;
    float sq = 0.f, sk = 0.f;
#pragma unroll
    for (int d = lane; d < HDD; d += 32) {
        float a = q[d]; sq = fmaf(a, a, sq);
        float c = k[d]; sk = fmaf(c, c, sk);
    }
#pragma unroll
    for (int o = 16; o; o >>= 1) {
        sq += __shfl_xor_sync(0xffffffffu, sq, o);
        sk += __shfl_xor_sync(0xffffffffu, sk, o);
    }
    if (lane == 0) {
        float n = fmaxf(sqrtf(sq), EPSS);
        qs[gw] = tanhf(n) / n;
        n = fmaxf(sqrtf(sk), EPSS);
        ks[gw] = tanhf(n) / n;
    }
}

// ---------------- scores[bh,i,j] = (qs[i]*isd) * kscale[j] * sum_d q[i,d]k[j,d] ----------------
// BM=BN=64, BK=32 (K=HD=128), 256 threads, 4x4 per thread.
__global__ __launch_bounds__(256) void k_scores(void) {
    __shared__ float Qs[32][64];
    __shared__ float Ks[32][64];

    const int bh = blockIdx.z;
    const int b = bh >> 3, h = bh & 7;
    const int tid = threadIdx.x;
    const int tx = tid & 15, ty = tid >> 4;
    const int i0 = blockIdx.y * 64, j0 = blockIdx.x * 64;

    const float* qbase = g_qkv + h * HDD;
    const float* kbase = g_qkv + HIDD + h * HDD;

    float acc[4][4];
#pragma unroll
    for (int i = 0; i < 4; i++)
#pragma unroll
        for (int j = 0; j < 4; j++) acc[i][j] = 0.f;

    for (int k0 = 0; k0 < HDD; k0 += 32) {
        // 64 rows x 32 cols per tile = 512 float4s; 2 per thread; do Q and K together
#pragma unroll
        for (int t = 0; t < 2; t++) {
            int f = tid + t * 256;
            int row = f >> 3, col4 = f & 7;

            int sI = i0 + row;
            float scq = g_qs[bh * SSQ + sI] * INV_SQRT_D;
            float4 v = *(const float4*)&qbase[(size_t)(b * SSQ + sI) * (3 * HIDD) + k0 + col4 * 4];
            Qs[col4 * 4 + 0][row] = v.x * scq;
            Qs[col4 * 4 + 1][row] = v.y * scq;
            Qs[col4 * 4 + 2][row] = v.z * scq;
            Qs[col4 * 4 + 3][row] = v.w * scq;

            int sJ = j0 + row;
            float sck = g_ks[bh * SSQ + sJ];
            float4 w = *(const float4*)&kbase[(size_t)(b * SSQ + sJ) * (3 * HIDD) + k0 + col4 * 4];
            Ks[col4 * 4 + 0][row] = w.x * sck;
            Ks[col4 * 4 + 1][row] = w.y * sck;
            Ks[col4 * 4 + 2][row] = w.z * sck;
            Ks[col4 * 4 + 3][row] = w.w * sck;
        }
        __syncthreads();
#pragma unroll
        for (int k = 0; k < 32; k++) {
            float rq[4], rk[4];
            *(float4*)rq = *(float4*)&Qs[k][ty * 4];
            *(float4*)rk = *(float4*)&Ks[k][tx * 4];
#pragma unroll
            for (int i = 0; i < 4; i++)
#pragma unroll
                for (int j = 0; j < 4; j++) acc[i][j] = fmaf(rq[i], rk[j], acc[i][j]);
        }
        __syncthreads();
    }

#pragma unroll
    for (int i = 0; i < 4; i++) {
        size_t off = ((size_t)bh * SSQ + i0 + ty * 4 + i) * SSQ + j0 + tx * 4;
        *(float4*)&g_scores[off] = make_float4(acc[i][0], acc[i][1], acc[i][2], acc[i][3]);
    }
}

// ---------------- row softmax over S=1024 (in place) ----------------
__global__ __launch_bounds__(256) void k_softmax(void) {
    __shared__ float red[256];
    size_t row = blockIdx.x;
    float* p = g_scores + row * SSQ;
    int tid = threadIdx.x;

    float4 v = *(float4*)&p[tid * 4];
    float mx = fmaxf(fmaxf(v.x, v.y), fmaxf(v.z, v.w));
    red[tid] = mx;
    __syncthreads();
#pragma unroll
    for (int s = 128; s > 0; s >>= 1) {
        if (tid < s) red[tid] = fmaxf(red[tid], red[tid + s]);
        __syncthreads();
    }
    mx = red[0];
    __syncthreads();

    v.x = expf(v.x - mx); v.y = expf(v.y - mx);
    v.z = expf(v.z - mx); v.w = expf(v.w - mx);
    red[tid] = v.x + v.y + v.z + v.w;
    __syncthreads();
#pragma unroll
    for (int s = 128; s > 0; s >>= 1) {
        if (tid < s) red[tid] += red[tid + s];
        __syncthreads();
    }
    float inv = 1.f / red[0];
    v.x *= inv; v.y *= inv; v.z *= inv; v.w *= inv;
    *(float4*)&p[tid * 4] = v;
}

// ---------------- O[bh,i,d] = sum_j P[bh,i,j] V[bh,j,d]  -> g_o[b,s,h*HD+d] ----------------
// BM=64, BN=128(all of HD), BK=16, 256 threads (16x16), thread tile 4x8.
__global__ __launch_bounds__(256) void k_av(void) {
    __shared__ float Ps[16][64];
    __shared__ float Vs[16][128];

    const int bh = blockIdx.y;
    const int b = bh >> 3, h = bh & 7;
    const int i0 = blockIdx.x * 64;
    const int tid = threadIdx.x;
    const int tx = tid & 15, ty = tid >> 4;

    const float* vbase = g_qkv + 2 * HIDD + h * HDD;

    float acc[4][8];
#pragma unroll
    for (int i = 0; i < 4; i++)
#pragma unroll
        for (int j = 0; j < 8; j++) acc[i][j] = 0.f;

    for (int k0 = 0; k0 < SSQ; k0 += 16) {
        // P tile 64x16 = 256 float4s, 1 per thread, transpose-scatter
        {
            int f = tid;
            int row = f >> 2, col4 = f & 3;
            float4 p4 = *(const float4*)&g_scores[((size_t)bh * SSQ + i0 + row) * SSQ + k0 + col4 * 4];
            Ps[col4 * 4 + 0][row] = p4.x;
            Ps[col4 * 4 + 1][row] = p4.y;
            Ps[col4 * 4 + 2][row] = p4.z;
            Ps[col4 * 4 + 3][row] = p4.w;
        }
        // V tile 16x128 = 512 float4s, 2 per thread, direct
#pragma unroll
        for (int t = 0; t < 2; t++) {
            int f = tid + t * 256;
            int row = f >> 5, col4 = f & 31;
            float4 v4 = *(const float4*)&vbase[(size_t)(b * SSQ + k0 + row) * (3 * HIDD) + col4 * 4];
            *(float4*)&Vs[row][col4 * 4] = v4;
        }
        __syncthreads();
#pragma unroll
        for (int k = 0; k < 16; k++) {
            float rp[4], rv[8];
            *(float4*)rp       = *(float4*)&Ps[k][ty * 4];
            *(float4*)(rv)     = *(float4*)&Vs[k][tx * 8];
            *(float4*)(rv + 4) = *(float4*)&Vs[k][tx * 8 + 4];
#pragma unroll
            for (int i = 0; i < 4; i++)
#pragma unroll
                for (int j = 0; j < 8; j++) acc[i][j] = fmaf(rp[i], rv[j], acc[i][j]);
        }
        __syncthreads();
    }

#pragma unroll
    for (int i = 0; i < 4; i++) {
        size_t off = (size_t)(b * SSQ + i0 + ty * 4 + i) * HIDD + h * HDD + tx * 8;
        *(float4*)&g_o[off]     = make_float4(acc[i][0], acc[i][1], acc[i][2], acc[i][3]);
        *(float4*)&g_o[off + 4] = make_float4(acc[i][4], acc[i][5], acc[i][6], acc[i][7]);
    }
}

// ---------------- manifold projection + residual update ----------------
// per row (b*S+s): m[8] = o_row @ W_pinv + b_pinv ; cur += m @ W_attn[l] + b_attn[l]
__global__ __launch_bounds__(256) void k_manifold(
    const float* __restrict__ Wp, const float* __restrict__ bp,
    const float* __restrict__ Wa, const float* __restrict__ ba)
{
    __shared__ float sO[HIDD];
    __shared__ float sm[MDD];
    const int row = blockIdx.x;
    const int tid = threadIdx.x;

    *(float4*)&sO[tid * 4] = *(const float4*)&g_o[(size_t)row * HIDD + tid * 4];
    __syncthreads();

    const int wid = tid >> 5, lane = tid & 31;
    float part = 0.f;
    for (int i = lane; i < HIDD; i += 32) part = fmaf(sO[i], Wp[i * MDD + wid], part);
#pragma unroll
    for (int o = 16; o; o >>= 1) part += __shfl_xor_sync(0xffffffffu, part, o);
    if (lane == 0) sm[wid] = part + bp[wid];
    __syncthreads();

    const int c = tid * 4;
    float4 u = *(const float4*)&ba[c];
#pragma unroll
    for (int mi = 0; mi < MDD; mi++) {
        float mv = sm[mi];
        float4 w = *(const float4*)&Wa[mi * HIDD + c];
        u.x = fmaf(mv, w.x, u.x);
        u.y = fmaf(mv, w.y, u.y);
        u.z = fmaf(mv, w.z, u.z);
        u.w = fmaf(mv, w.w, u.w);
    }
    size_t off = (size_t)row * HIDD + c;
    float4 cv = *(float4*)&g_cur[off];
    cv.x += u.x; cv.y += u.y; cv.z += u.z; cv.w += u.w;
    *(float4*)&g_cur[off] = cv;
}

// ---------------- launcher ----------------
extern "C" void kernel_launch(void* const* d_in, const int* in_sizes, int n_in,
                              void* d_out, int out_size) {
    (void)in_sizes; (void)n_in; (void)out_size;
    const float* x      = (const float*)d_in[0];
    const float* W_qkv  = (const float*)d_in[1];
    const float* b_qkv  = (const float*)d_in[2];
    const float* W_pinv = (const float*)d_in[3];
    const float* b_pinv = (const float*)d_in[4];
    const float* W_attn = (const float*)d_in[5];
    const float* b_attn = (const float*)d_in[6];
    const float* W_out  = (const float*)d_in[7];
    const float* b_out  = (const float*)d_in[8];
    float* out = (float*)d_out;

    float *p_cur, *p_qkv;
    cudaGetSymbolAddress((void**)&p_cur, g_cur);
    cudaGetSymbolAddress((void**)&p_qkv, g_qkv);

    // cur = x
    {
        int n4 = BB * SSQ * HIDD / 4;
        k_copy4<<<(n4 + 255) / 256, 256>>>((const float4*)x, (float4*)p_cur, n4);
    }

    for (int l = 0; l < NL; l++) {
        // qkv = cur @ W_qkv + b_qkv   [8192 x 3072]
        k_sgemm_bias<<<dim3(3 * HIDD / 128, BB * SSQ / 128), 256>>>(
            p_cur, W_qkv, b_qkv, p_qkv, BB * SSQ, 3 * HIDD, HIDD);

        // expmap0 row scales
        {
            float *pq, *pk;
            cudaGetSymbolAddress((void**)&pq, g_qs);
            cudaGetSymbolAddress((void**)&pk, g_ks);
            int warps = BB * NH * SSQ;
            k_scales<<<warps * 32 / 256, 256>>>(p_qkv, pq, pk);
        }

        // scores
        k_scores<<<dim3(SSQ / 64, SSQ / 64, BB * NH), 256>>>();
        // softmax
        k_softmax<<<BB * NH * SSQ, 256>>>();
        // O = P @ V
        k_av<<<dim3(SSQ / 64, BB * NH), 256>>>();
        // manifold projection + residual
        k_manifold<<<BB * SSQ, 256>>>(W_pinv, b_pinv,
                                      W_attn + (size_t)l * MDD * HIDD,
                                      b_attn + (size_t)l * HIDD);
    }

    // out = cur @ W_out + b_out   [8192 x 1024]
    k_sgemm_bias<<<dim3(HIDD / 128, BB * SSQ / 128), 256>>>(
        p_cur, W_out, b_out, out, BB * SSQ, HIDD, HIDD);
}

// round 2
// speedup vs baseline: 2.3709x; 2.3709x over previous
#include <cuda_runtime.h>
#include <math.h>
#include <stdint.h>

// ---------------- problem constants ----------------
#define BB   8
#define SSQ  1024
#define HIDD 1024
#define NH   8
#define HDD  128
#define MDD  8
#define NL   3
#define EPSS 1e-7f
#define INV_SQRT_D 0.08838834764831845f   // 1/sqrt(128)

// ---------------- scratch (device globals; no cudaMalloc allowed) ----------------
__device__ float g_cur   [BB * SSQ * HIDD];            // 32 MB
__device__ float g_qkv   [BB * SSQ * 3 * HIDD];        // 100 MB
__device__ float g_scores[(size_t)BB * NH * SSQ * SSQ];// 256 MB
__device__ float g_o     [BB * SSQ * HIDD];            // 32 MB
__device__ float g_qs    [BB * NH * SSQ];
__device__ float g_ks    [BB * NH * SSQ];
__device__ float g_wtq   [3 * HIDD * HIDD];            // W_qkv^T  [3072][1024], 12 MB
__device__ float g_wto   [HIDD * HIDD];                // W_out^T  [1024][1024], 4 MB
__device__ float g_vt    [BB * NH * HDD * SSQ];        // V^T per head [bh][d][s], 32 MB

// ---------------- helpers ----------------
__device__ __forceinline__ uint32_t f2tf(float x) {
    uint32_t u;
    asm("cvt.rna.tf32.f32 %0, %1;" : "=r"(u) : "f"(x));
    return u;
}

__global__ void k_copy4(const float4* __restrict__ src, float4* __restrict__ dst, int n4) {
    int i = blockIdx.x * blockDim.x + threadIdx.x;
    if (i < n4) dst[i] = src[i];
}

// dst[n*K + k] = src[k*N + n]   (tiled transpose, block 32x8)
__global__ void k_transpose(const float* __restrict__ src, float* __restrict__ dst, int K, int N) {
    __shared__ float t[32][33];
    int n0 = blockIdx.x * 32, k0 = blockIdx.y * 32;
    int tx = threadIdx.x, ty = threadIdx.y;
#pragma unroll
    for (int j = 0; j < 32; j += 8)
        t[ty + j][tx] = src[(size_t)(k0 + ty + j) * N + n0 + tx];
    __syncthreads();
#pragma unroll
    for (int j = 0; j < 32; j += 8)
        dst[(size_t)(n0 + ty + j) * K + k0 + tx] = t[tx][ty + j];
}

// g_vt[bh][d][s] = V[b,s,h,d]  (V lives in g_qkv at column offset 2*HIDD)
__global__ void k_vt(void) {
    __shared__ float t[32][33];
    int z = blockIdx.z; int b = z >> 3, h = z & 7;
    int s0 = blockIdx.x * 32, d0 = blockIdx.y * 32;
    int tx = threadIdx.x, ty = threadIdx.y;
    const float* src = g_qkv + (size_t)b * SSQ * 3 * HIDD + 2 * HIDD + h * HDD;
#pragma unroll
    for (int j = 0; j < 32; j += 8)
        t[ty + j][tx] = src[(size_t)(s0 + ty + j) * (3 * HIDD) + d0 + tx];
    __syncthreads();
    float* dst = g_vt + (size_t)z * HDD * SSQ;
#pragma unroll
    for (int j = 0; j < 32; j += 8)
        dst[(size_t)(d0 + ty + j) * SSQ + s0 + tx] = t[tx][ty + j];
}

// ---------------- unified tf32 tensor-core GEMM ----------------
// C[m,n] = sum_k A[m,k] * B[n,k]  (+ bias[n]), optional per-row scales on A and B rows.
// Block tile 128x128, BK=32, 256 threads (8 warps as 2(m) x 4(n), warp tile 64x32).
// z-batching: base pointers offset by (z/8)*s1 + (z%8)*s2.
#define PAD 36

__global__ __launch_bounds__(256) void k_mma(
    const float* __restrict__ Abase, long long sA1, long long sA2, int lda,
    const float* __restrict__ Bbase, long long sB1, long long sB2, int ldb,
    float*       __restrict__ Cbase, long long sC1, long long sC2, int ldc,
    const float* __restrict__ bias,
    const float* __restrict__ ascBase, long long sas1, long long sas2,
    const float* __restrict__ bscBase, long long sbs1, long long sbs2,
    int K)
{
    __shared__ uint32_t As[128 * PAD];
    __shared__ uint32_t Bs[128 * PAD];

    const int z = blockIdx.z;
    const long long zh = z >> 3, zl = z & 7;
    const float* A = Abase + zh * sA1 + zl * sA2;
    const float* B = Bbase + zh * sB1 + zl * sB2;
    float*       C = Cbase + zh * sC1 + zl * sC2;
    const float* asc = ascBase ? (ascBase + zh * sas1 + zl * sas2) : nullptr;
    const float* bsc = bscBase ? (bscBase + zh * sbs1 + zl * sbs2) : nullptr;

    const int m0 = blockIdx.y * 128;
    const int n0 = blockIdx.x * 128;
    const int tid = threadIdx.x;
    const int w = tid >> 5, lane = tid & 31;
    const int wm = w & 1, wn = w >> 1;       // warp tile origin (wm*64, wn*32)
    const int g = lane >> 2, tg = lane & 3;  // groupID, threadID_in_group

    float acc[4][4][4];
#pragma unroll
    for (int mi = 0; mi < 4; mi++)
#pragma unroll
        for (int ni = 0; ni < 4; ni++)
#pragma unroll
            for (int r = 0; r < 4; r++) acc[mi][ni][r] = 0.f;

    for (int k0 = 0; k0 < K; k0 += 32) {
        // stage A tile: 128 rows x 32 k, cvt to tf32 during store
#pragma unroll
        for (int i = 0; i < 4; i++) {
            int f = tid + i * 256;
            int r = f >> 3, c4 = f & 7;
            float4 v = *(const float4*)(A + (size_t)(m0 + r) * lda + k0 + c4 * 4);
            if (asc) { float s = asc[m0 + r]; v.x *= s; v.y *= s; v.z *= s; v.w *= s; }
            uint32_t* p = &As[r * PAD + c4 * 4];
            p[0] = f2tf(v.x); p[1] = f2tf(v.y); p[2] = f2tf(v.z); p[3] = f2tf(v.w);
        }
        // stage B tile: 128 n-rows x 32 k
#pragma unroll
        for (int i = 0; i < 4; i++) {
            int f = tid + i * 256;
            int r = f >> 3, c4 = f & 7;
            float4 v = *(const float4*)(B + (size_t)(n0 + r) * ldb + k0 + c4 * 4);
            if (bsc) { float s = bsc[n0 + r]; v.x *= s; v.y *= s; v.z *= s; v.w *= s; }
            uint32_t* p = &Bs[r * PAD + c4 * 4];
            p[0] = f2tf(v.x); p[1] = f2tf(v.y); p[2] = f2tf(v.z); p[3] = f2tf(v.w);
        }
        __syncthreads();

#pragma unroll
        for (int kk = 0; kk < 32; kk += 8) {
            uint32_t af[4][4], bf[4][2];
#pragma unroll
            for (int mi = 0; mi < 4; mi++) {
                int base = (wm * 64 + mi * 16 + g) * PAD + kk + tg;
                af[mi][0] = As[base];
                af[mi][1] = As[base + 8 * PAD];
                af[mi][2] = As[base + 4];
                af[mi][3] = As[base + 8 * PAD + 4];
            }
#pragma unroll
            for (int ni = 0; ni < 4; ni++) {
                int base = (wn * 32 + ni * 8 + g) * PAD + kk + tg;
                bf[ni][0] = Bs[base];
                bf[ni][1] = Bs[base + 4];
            }
#pragma unroll
            for (int mi = 0; mi < 4; mi++)
#pragma unroll
                for (int ni = 0; ni < 4; ni++) {
                    asm volatile(
                        "mma.sync.aligned.m16n8k8.row.col.f32.tf32.tf32.f32 "
                        "{%0,%1,%2,%3}, {%4,%5,%6,%7}, {%8,%9}, {%0,%1,%2,%3};\n"
                        : "+f"(acc[mi][ni][0]), "+f"(acc[mi][ni][1]),
                          "+f"(acc[mi][ni][2]), "+f"(acc[mi][ni][3])
                        : "r"(af[mi][0]), "r"(af[mi][1]), "r"(af[mi][2]), "r"(af[mi][3]),
                          "r"(bf[ni][0]), "r"(bf[ni][1]));
                }
        }
        __syncthreads();
    }

    // epilogue
#pragma unroll
    for (int mi = 0; mi < 4; mi++) {
        int r0 = m0 + wm * 64 + mi * 16 + g;
#pragma unroll
        for (int ni = 0; ni < 4; ni++) {
            int c = n0 + wn * 32 + ni * 8 + 2 * tg;
            float b0 = 0.f, b1 = 0.f;
            if (bias) { b0 = bias[c]; b1 = bias[c + 1]; }
            float2 v;
            v.x = acc[mi][ni][0] + b0; v.y = acc[mi][ni][1] + b1;
            *(float2*)(C + (size_t)r0 * ldc + c) = v;
            v.x = acc[mi][ni][2] + b0; v.y = acc[mi][ni][3] + b1;
            *(float2*)(C + (size_t)(r0 + 8) * ldc + c) = v;
        }
    }
}

// ---------------- expmap0 row scales (q scale folded with 1/sqrt(d)) ----------------
__global__ void k_scales(const float* __restrict__ qkv, float* __restrict__ qs, float* __restrict__ ks) {
    int gw = (blockIdx.x * blockDim.x + threadIdx.x) >> 5;
    int lane = threadIdx.x & 31;
    if (gw >= BB * NH * SSQ) return;
    int s = gw & (SSQ - 1);
    int bh = gw >> 10;
    int b = bh >> 3, h = bh & 7;
    const float* q = qkv + (size_t)(b * SSQ + s) * (3 * HIDD) + h * HDD;
    const float* k = q + HIDD;
    float sq = 0.f, sk = 0.f;
#pragma unroll
    for (int d = lane; d < HDD; d += 32) {
        float a = q[d]; sq = fmaf(a, a, sq);
        float c = k[d]; sk = fmaf(c, c, sk);
    }
#pragma unroll
    for (int o = 16; o; o >>= 1) {
        sq += __shfl_xor_sync(0xffffffffu, sq, o);
        sk += __shfl_xor_sync(0xffffffffu, sk, o);
    }
    if (lane == 0) {
        float n = fmaxf(sqrtf(sq), EPSS);
        qs[gw] = tanhf(n) / n * INV_SQRT_D;
        n = fmaxf(sqrtf(sk), EPSS);
        ks[gw] = tanhf(n) / n;
    }
}

// ---------------- row softmax over S=1024 (in place) ----------------
__global__ __launch_bounds__(256) void k_softmax(void) {
    __shared__ float red[256];
    size_t row = blockIdx.x;
    float* p = g_scores + row * SSQ;
    int tid = threadIdx.x;

    float4 v = *(float4*)&p[tid * 4];
    float mx = fmaxf(fmaxf(v.x, v.y), fmaxf(v.z, v.w));
    red[tid] = mx;
    __syncthreads();
#pragma unroll
    for (int s = 128; s > 0; s >>= 1) {
        if (tid < s) red[tid] = fmaxf(red[tid], red[tid + s]);
        __syncthreads();
    }
    mx = red[0];
    __syncthreads();

    v.x = expf(v.x - mx); v.y = expf(v.y - mx);
    v.z = expf(v.z - mx); v.w = expf(v.w - mx);
    red[tid] = v.x + v.y + v.z + v.w;
    __syncthreads();
#pragma unroll
    for (int s = 128; s > 0; s >>= 1) {
        if (tid < s) red[tid] += red[tid + s];
        __syncthreads();
    }
    float inv = 1.f / red[0];
    v.x *= inv; v.y *= inv; v.z *= inv; v.w *= inv;
    *(float4*)&p[tid * 4] = v;
}

// ---------------- manifold projection + residual update ----------------
__global__ __launch_bounds__(256) void k_manifold(
    const float* __restrict__ Wp, const float* __restrict__ bp,
    const float* __restrict__ Wa, const float* __restrict__ ba)
{
    __shared__ float sO[HIDD];
    __shared__ float sm[MDD];
    const int row = blockIdx.x;
    const int tid = threadIdx.x;

    *(float4*)&sO[tid * 4] = *(const float4*)&g_o[(size_t)row * HIDD + tid * 4];
    __syncthreads();

    const int wid = tid >> 5, lane = tid & 31;
    float part = 0.f;
    for (int i = lane; i < HIDD; i += 32) part = fmaf(sO[i], Wp[i * MDD + wid], part);
#pragma unroll
    for (int o = 16; o; o >>= 1) part += __shfl_xor_sync(0xffffffffu, part, o);
    if (lane == 0) sm[wid] = part + bp[wid];
    __syncthreads();

    const int c = tid * 4;
    float4 u = *(const float4*)&ba[c];
#pragma unroll
    for (int mi = 0; mi < MDD; mi++) {
        float mv = sm[mi];
        float4 w = *(const float4*)&Wa[mi * HIDD + c];
        u.x = fmaf(mv, w.x, u.x);
        u.y = fmaf(mv, w.y, u.y);
        u.z = fmaf(mv, w.z, u.z);
        u.w = fmaf(mv, w.w, u.w);
    }
    size_t off = (size_t)row * HIDD + c;
    float4 cv = *(float4*)&g_cur[off];
    cv.x += u.x; cv.y += u.y; cv.z += u.z; cv.w += u.w;
    *(float4*)&g_cur[off] = cv;
}

// ---------------- launcher ----------------
extern "C" void kernel_launch(void* const* d_in, const int* in_sizes, int n_in,
                              void* d_out, int out_size) {
    (void)in_sizes; (void)n_in; (void)out_size;
    const float* x      = (const float*)d_in[0];
    const float* W_qkv  = (const float*)d_in[1];
    const float* b_qkv  = (const float*)d_in[2];
    const float* W_pinv = (const float*)d_in[3];
    const float* b_pinv = (const float*)d_in[4];
    const float* W_attn = (const float*)d_in[5];
    const float* b_attn = (const float*)d_in[6];
    const float* W_out  = (const float*)d_in[7];
    const float* b_out  = (const float*)d_in[8];
    float* out = (float*)d_out;

    float *p_cur, *p_qkv, *p_scores, *p_o, *p_qs, *p_ks, *p_wtq, *p_wto, *p_vt;
    cudaGetSymbolAddress((void**)&p_cur, g_cur);
    cudaGetSymbolAddress((void**)&p_qkv, g_qkv);
    cudaGetSymbolAddress((void**)&p_scores, g_scores);
    cudaGetSymbolAddress((void**)&p_o, g_o);
    cudaGetSymbolAddress((void**)&p_qs, g_qs);
    cudaGetSymbolAddress((void**)&p_ks, g_ks);
    cudaGetSymbolAddress((void**)&p_wtq, g_wtq);
    cudaGetSymbolAddress((void**)&p_wto, g_wto);
    cudaGetSymbolAddress((void**)&p_vt, g_vt);

    // cur = x
    {
        int n4 = BB * SSQ * HIDD / 4;
        k_copy4<<<(n4 + 255) / 256, 256>>>((const float4*)x, (float4*)p_cur, n4);
    }
    // transpose weights (loop-invariant)
    k_transpose<<<dim3(3 * HIDD / 32, HIDD / 32), dim3(32, 8)>>>(W_qkv, p_wtq, HIDD, 3 * HIDD);
    k_transpose<<<dim3(HIDD / 32, HIDD / 32), dim3(32, 8)>>>(W_out, p_wto, HIDD, HIDD);

    const long long M1 = 1024 * 1024;  // SSQ*SSQ

    for (int l = 0; l < NL; l++) {
        // qkv = cur @ W_qkv + b_qkv   (M=8192, N=3072, K=1024)
        k_mma<<<dim3(3 * HIDD / 128, BB * SSQ / 128, 1), 256>>>(
            p_cur, 0, 0, HIDD,
            p_wtq, 0, 0, HIDD,
            p_qkv, 0, 0, 3 * HIDD,
            b_qkv,
            nullptr, 0, 0, nullptr, 0, 0,
            HIDD);

        // expmap0 row scales
        k_scales<<<BB * NH * SSQ * 32 / 256, 256>>>(p_qkv, p_qs, p_ks);

        // V^T per head
        k_vt<<<dim3(SSQ / 32, HDD / 32, BB * NH), dim3(32, 8)>>>();

        // scores[bh] = (qs.Q) @ (ks.K)^T   (M=N=1024, K=128, batched over 64 bh)
        k_mma<<<dim3(SSQ / 128, SSQ / 128, BB * NH), 256>>>(
            p_qkv,        (long long)SSQ * 3 * HIDD, HDD, 3 * HIDD,
            p_qkv + HIDD, (long long)SSQ * 3 * HIDD, HDD, 3 * HIDD,
            p_scores,     8 * M1, M1, SSQ,
            nullptr,
            p_qs, 8LL * SSQ, SSQ,
            p_ks, 8LL * SSQ, SSQ,
            HDD);

        // softmax rows
        k_softmax<<<BB * NH * SSQ, 256>>>();

        // O[bh] = P @ V   (M=1024, N=128, K=1024; B = V^T natural layout)
        k_mma<<<dim3(HDD / 128, SSQ / 128, BB * NH), 256>>>(
            p_scores, 8 * M1, M1, SSQ,
            p_vt,     8LL * HDD * SSQ, (long long)HDD * SSQ, SSQ,
            p_o,      M1, HDD, HIDD,
            nullptr,
            nullptr, 0, 0, nullptr, 0, 0,
            SSQ);

        // manifold projection + residual
        k_manifold<<<BB * SSQ, 256>>>(W_pinv, b_pinv,
                                      W_attn + (size_t)l * MDD * HIDD,
                                      b_attn + (size_t)l * HIDD);
    }

    // out = cur @ W_out + b_out   (M=8192, N=1024, K=1024)
    k_mma<<<dim3(HIDD / 128, BB * SSQ / 128, 1), 256>>>(
        p_cur, 0, 0, HIDD,
        p_wto, 0, 0, HIDD,
        out,   0, 0, HIDD,
        b_out,
        nullptr, 0, 0, nullptr, 0, 0,
        HIDD);
}

// round 7
// speedup vs baseline: 2.8419x; 1.1986x over previous
#include <cuda_runtime.h>
#include <math.h>
#include <stdint.h>

// ---------------- problem constants ----------------
#define BB   8
#define SSQ  1024
#define HIDD 1024
#define NH   8
#define HDD  128
#define MDD  8
#define NL   3
#define EPSS 1e-7f
#define INV_SQRT_D 0.08838834764831845f   // 1/sqrt(128)

// ---------------- scratch (device globals; no cudaMalloc allowed) ----------------
__device__ float g_cur   [BB * SSQ * HIDD];            // fp32 residual stream
__device__ float g_curt  [BB * SSQ * HIDD];            // tf32-rounded shadow of cur
__device__ float g_qkv   [BB * SSQ * 3 * HIDD];        // q,k get scaled+rounded in place
__device__ float g_scores[(size_t)BB * NH * SSQ * SSQ];
__device__ float g_o     [BB * SSQ * HIDD];
__device__ float g_wtq   [3 * HIDD * HIDD];            // W_qkv^T (rounded)
__device__ float g_wto   [HIDD * HIDD];                // W_out^T (rounded)
__device__ float g_vt    [BB * NH * HDD * SSQ];        // V^T per head (rounded)

// ---------------- helpers ----------------
__device__ __forceinline__ uint32_t f2tf(float x) {
    uint32_t u;
    asm("cvt.rna.tf32.f32 %0, %1;" : "=r"(u) : "f"(x));
    return u;
}
__device__ __forceinline__ float f2tff(float x) { return __uint_as_float(f2tf(x)); }

__device__ __forceinline__ void cpa16(uint32_t dst, const float* src) {
    asm volatile("cp.async.cg.shared.global [%0], [%1], 16;\n" :: "r"(dst), "l"(src));
}
__device__ __forceinline__ void cpa_commit(void) {
    asm volatile("cp.async.commit_group;\n");
}

// copy x -> g_cur (exact) and g_curt (tf32-rounded)
__global__ void k_copy_round(const float4* __restrict__ src, float4* __restrict__ dst,
                             float4* __restrict__ dstr, int n4) {
    int i = blockIdx.x * blockDim.x + threadIdx.x;
    if (i >= n4) return;
    float4 v = src[i];
    dst[i] = v;
    float4 r = make_float4(f2tff(v.x), f2tff(v.y), f2tff(v.z), f2tff(v.w));
    dstr[i] = r;
}

// dst[n*K + k] = round(src[k*N + n])
__global__ void k_transpose(const float* __restrict__ src, float* __restrict__ dst, int K, int N) {
    __shared__ float t[32][33];
    int n0 = blockIdx.x * 32, k0 = blockIdx.y * 32;
    int tx = threadIdx.x, ty = threadIdx.y;
#pragma unroll
    for (int j = 0; j < 32; j += 8)
        t[ty + j][tx] = src[(size_t)(k0 + ty + j) * N + n0 + tx];
    __syncthreads();
#pragma unroll
    for (int j = 0; j < 32; j += 8)
        dst[(size_t)(n0 + ty + j) * K + k0 + tx] = f2tff(t[tx][ty + j]);
}

// g_vt[bh][d][s] = round(V[b,s,h,d])
__global__ void k_vt(void) {
    __shared__ float t[32][33];
    int z = blockIdx.z; int b = z >> 3, h = z & 7;
    int s0 = blockIdx.x * 32, d0 = blockIdx.y * 32;
    int tx = threadIdx.x, ty = threadIdx.y;
    const float* src = g_qkv + (size_t)b * SSQ * 3 * HIDD + 2 * HIDD + h * HDD;
#pragma unroll
    for (int j = 0; j < 32; j += 8)
        t[ty + j][tx] = src[(size_t)(s0 + ty + j) * (3 * HIDD) + d0 + tx];
    __syncthreads();
    float* dst = g_vt + (size_t)z * HDD * SSQ;
#pragma unroll
    for (int j = 0; j < 32; j += 8)
        dst[(size_t)(d0 + ty + j) * SSQ + s0 + tx] = f2tff(t[tx][ty + j]);
}

// ---------------- expmap0: scale + round q,k in place ----------------
__global__ void k_scales_apply(void) {
    int gw = (blockIdx.x * blockDim.x + threadIdx.x) >> 5;  // one warp per (b,h,s)
    int lane = threadIdx.x & 31;
    if (gw >= BB * NH * SSQ) return;
    int s = gw & (SSQ - 1);
    int bh = gw >> 10;
    int b = bh >> 3, h = bh & 7;
    float* q = g_qkv + (size_t)(b * SSQ + s) * (3 * HIDD) + h * HDD;
    float* k = q + HIDD;
    float qv[4], kv[4];
    float sq = 0.f, sk = 0.f;
#pragma unroll
    for (int j = 0; j < 4; j++) {
        int d = lane + 32 * j;
        qv[j] = q[d]; sq = fmaf(qv[j], qv[j], sq);
        kv[j] = k[d]; sk = fmaf(kv[j], kv[j], sk);
    }
#pragma unroll
    for (int o = 16; o; o >>= 1) {
        sq += __shfl_xor_sync(0xffffffffu, sq, o);
        sk += __shfl_xor_sync(0xffffffffu, sk, o);
    }
    float nq = fmaxf(sqrtf(sq), EPSS);
    float scq = tanhf(nq) / nq * INV_SQRT_D;
    float nk = fmaxf(sqrtf(sk), EPSS);
    float sck = tanhf(nk) / nk;
#pragma unroll
    for (int j = 0; j < 4; j++) {
        int d = lane + 32 * j;
        q[d] = f2tff(qv[j] * scq);
        k[d] = f2tff(kv[j] * sck);
    }
}

// ---------------- pipelined tf32 tensor-core GEMM ----------------
// C[m,n] = sum_k A[m,k] * B[n,k] (+ bias[n]). All operands pre-rounded tf32 bits.
// Block 128x128, BK=16, 256 threads (8 warps: 2m x 4n, warp tile 64x32).
// 2-stage cp.async pipeline, STATIC shared memory (40 KB total, no opt-in).
// z-batch: base += (z/8)*s1 + (z%8)*s2.
#define PAD 20
#define STG_WORDS (128 * PAD)

__device__ __forceinline__ void load_stage(
    uint32_t* as, uint32_t* bs,
    const float* A, const float* B, int lda, int ldb,
    int m0, int n0, int k0, int rr, int cc)
{
#pragma unroll
    for (int i = 0; i < 2; i++) {
        int row = rr + i * 64;
        cpa16((uint32_t)__cvta_generic_to_shared(as + row * PAD + cc),
              A + (size_t)(m0 + row) * lda + k0 + cc);
        cpa16((uint32_t)__cvta_generic_to_shared(bs + row * PAD + cc),
              B + (size_t)(n0 + row) * ldb + k0 + cc);
    }
    cpa_commit();
}

__global__ __launch_bounds__(256) void k_mma(
    const float* __restrict__ Abase, long long sA1, long long sA2, int lda,
    const float* __restrict__ Bbase, long long sB1, long long sB2, int ldb,
    float*       __restrict__ Cbase, long long sC1, long long sC2, int ldc,
    const float* __restrict__ bias, int K)
{
    __shared__ uint32_t As[2][STG_WORDS];   // 2 stages x 128 rows x PAD
    __shared__ uint32_t Bs[2][STG_WORDS];

    const int z = blockIdx.z;
    const long long zh = z >> 3, zl = z & 7;
    const float* A = Abase + zh * sA1 + zl * sA2;
    const float* B = Bbase + zh * sB1 + zl * sB2;
    float*       C = Cbase + zh * sC1 + zl * sC2;

    const int m0 = blockIdx.y * 128;
    const int n0 = blockIdx.x * 128;
    const int tid = threadIdx.x;
    const int w = tid >> 5, lane = tid & 31;
    const int wm = w & 1, wn = w >> 1;
    const int g = lane >> 2, tg = lane & 3;

    const int rr = tid >> 2;          // staging row base (0..63)
    const int cc = (tid & 3) * 4;     // k-offset (floats) of 16B chunk

    float acc[4][4][4];
#pragma unroll
    for (int mi = 0; mi < 4; mi++)
#pragma unroll
        for (int ni = 0; ni < 4; ni++)
#pragma unroll
            for (int r = 0; r < 4; r++) acc[mi][ni][r] = 0.f;

    const int nc = K >> 4;  // K/16 chunks (always >= 8 here)
    load_stage(As[0], Bs[0], A, B, lda, ldb, m0, n0, 0, rr, cc);
    load_stage(As[1], Bs[1], A, B, lda, ldb, m0, n0, 16, rr, cc);

    for (int c = 0; c < nc; c++) {
        if (c + 1 < nc) asm volatile("cp.async.wait_group 1;\n");
        else            asm volatile("cp.async.wait_group 0;\n");
        __syncthreads();

        const uint32_t* as = As[c & 1];
        const uint32_t* bs = Bs[c & 1];

#pragma unroll
        for (int kk = 0; kk < 16; kk += 8) {
            uint32_t af[4][4], bf[4][2];
#pragma unroll
            for (int mi = 0; mi < 4; mi++) {
                int base = (wm * 64 + mi * 16 + g) * PAD + kk + tg;
                af[mi][0] = as[base];
                af[mi][1] = as[base + 8 * PAD];
                af[mi][2] = as[base + 4];
                af[mi][3] = as[base + 8 * PAD + 4];
            }
#pragma unroll
            for (int ni = 0; ni < 4; ni++) {
                int base = (wn * 32 + ni * 8 + g) * PAD + kk + tg;
                bf[ni][0] = bs[base];
                bf[ni][1] = bs[base + 4];
            }
#pragma unroll
            for (int mi = 0; mi < 4; mi++)
#pragma unroll
                for (int ni = 0; ni < 4; ni++) {
                    asm volatile(
                        "mma.sync.aligned.m16n8k8.row.col.f32.tf32.tf32.f32 "
                        "{%0,%1,%2,%3}, {%4,%5,%6,%7}, {%8,%9}, {%0,%1,%2,%3};\n"
                        : "+f"(acc[mi][ni][0]), "+f"(acc[mi][ni][1]),
                          "+f"(acc[mi][ni][2]), "+f"(acc[mi][ni][3])
                        : "r"(af[mi][0]), "r"(af[mi][1]), "r"(af[mi][2]), "r"(af[mi][3]),
                          "r"(bf[ni][0]), "r"(bf[ni][1]));
                }
        }
        __syncthreads();
        if (c + 2 < nc)
            load_stage(As[c & 1], Bs[c & 1], A, B, lda, ldb, m0, n0, (c + 2) * 16, rr, cc);
    }

    // epilogue
#pragma unroll
    for (int mi = 0; mi < 4; mi++) {
        int r0 = m0 + wm * 64 + mi * 16 + g;
#pragma unroll
        for (int ni = 0; ni < 4; ni++) {
            int c = n0 + wn * 32 + ni * 8 + 2 * tg;
            float b0 = 0.f, b1 = 0.f;
            if (bias) { b0 = bias[c]; b1 = bias[c + 1]; }
            float2 v;
            v.x = acc[mi][ni][0] + b0; v.y = acc[mi][ni][1] + b1;
            *(float2*)(C + (size_t)r0 * ldc + c) = v;
            v.x = acc[mi][ni][2] + b0; v.y = acc[mi][ni][3] + b1;
            *(float2*)(C + (size_t)(r0 + 8) * ldc + c) = v;
        }
    }
}

// ---------------- row softmax over S=1024 (in place, rounds output to tf32) ----------------
__global__ __launch_bounds__(256) void k_softmax(void) {
    __shared__ float red[256];
    size_t row = blockIdx.x;
    float* p = g_scores + row * SSQ;
    int tid = threadIdx.x;

    float4 v = *(float4*)&p[tid * 4];
    float mx = fmaxf(fmaxf(v.x, v.y), fmaxf(v.z, v.w));
    red[tid] = mx;
    __syncthreads();
#pragma unroll
    for (int s = 128; s > 0; s >>= 1) {
        if (tid < s) red[tid] = fmaxf(red[tid], red[tid + s]);
        __syncthreads();
    }
    mx = red[0];
    __syncthreads();

    v.x = expf(v.x - mx); v.y = expf(v.y - mx);
    v.z = expf(v.z - mx); v.w = expf(v.w - mx);
    red[tid] = v.x + v.y + v.z + v.w;
    __syncthreads();
#pragma unroll
    for (int s = 128; s > 0; s >>= 1) {
        if (tid < s) red[tid] += red[tid + s];
        __syncthreads();
    }
    float inv = 1.f / red[0];
    v.x = f2tff(v.x * inv); v.y = f2tff(v.y * inv);
    v.z = f2tff(v.z * inv); v.w = f2tff(v.w * inv);
    *(float4*)&p[tid * 4] = v;
}

// ---------------- manifold projection + residual update (also refresh rounded shadow) ----------------
__global__ __launch_bounds__(256) void k_manifold(
    const float* __restrict__ Wp, const float* __restrict__ bp,
    const float* __restrict__ Wa, const float* __restrict__ ba)
{
    __shared__ float sO[HIDD];
    __shared__ float sm[MDD];
    const int row = blockIdx.x;
    const int tid = threadIdx.x;

    *(float4*)&sO[tid * 4] = *(const float4*)&g_o[(size_t)row * HIDD + tid * 4];
    __syncthreads();

    const int wid = tid >> 5, lane = tid & 31;
    float part = 0.f;
    for (int i = lane; i < HIDD; i += 32) part = fmaf(sO[i], Wp[i * MDD + wid], part);
#pragma unroll
    for (int o = 16; o; o >>= 1) part += __shfl_xor_sync(0xffffffffu, part, o);
    if (lane == 0) sm[wid] = part + bp[wid];
    __syncthreads();

    const int c = tid * 4;
    float4 u = *(const float4*)&ba[c];
#pragma unroll
    for (int mi = 0; mi < MDD; mi++) {
        float mv = sm[mi];
        float4 w = *(const float4*)&Wa[mi * HIDD + c];
        u.x = fmaf(mv, w.x, u.x);
        u.y = fmaf(mv, w.y, u.y);
        u.z = fmaf(mv, w.z, u.z);
        u.w = fmaf(mv, w.w, u.w);
    }
    size_t off = (size_t)row * HIDD + c;
    float4 cv = *(float4*)&g_cur[off];
    cv.x += u.x; cv.y += u.y; cv.z += u.z; cv.w += u.w;
    *(float4*)&g_cur[off] = cv;
    float4 rv = make_float4(f2tff(cv.x), f2tff(cv.y), f2tff(cv.z), f2tff(cv.w));
    *(float4*)&g_curt[off] = rv;
}

// ---------------- launcher ----------------
extern "C" void kernel_launch(void* const* d_in, const int* in_sizes, int n_in,
                              void* d_out, int out_size) {
    (void)in_sizes; (void)n_in; (void)out_size;
    const float* x      = (const float*)d_in[0];
    const float* W_qkv  = (const float*)d_in[1];
    const float* b_qkv  = (const float*)d_in[2];
    const float* W_pinv = (const float*)d_in[3];
    const float* b_pinv = (const float*)d_in[4];
    const float* W_attn = (const float*)d_in[5];
    const float* b_attn = (const float*)d_in[6];
    const float* W_out  = (const float*)d_in[7];
    const float* b_out  = (const float*)d_in[8];
    float* out = (float*)d_out;

    float *p_cur, *p_curt, *p_qkv, *p_scores, *p_o, *p_wtq, *p_wto, *p_vt;
    cudaGetSymbolAddress((void**)&p_cur, g_cur);
    cudaGetSymbolAddress((void**)&p_curt, g_curt);
    cudaGetSymbolAddress((void**)&p_qkv, g_qkv);
    cudaGetSymbolAddress((void**)&p_scores, g_scores);
    cudaGetSymbolAddress((void**)&p_o, g_o);
    cudaGetSymbolAddress((void**)&p_wtq, g_wtq);
    cudaGetSymbolAddress((void**)&p_wto, g_wto);
    cudaGetSymbolAddress((void**)&p_vt, g_vt);

    // cur = x (exact + rounded shadow)
    {
        int n4 = BB * SSQ * HIDD / 4;
        k_copy_round<<<(n4 + 255) / 256, 256>>>((const float4*)x, (float4*)p_cur,
                                                (float4*)p_curt, n4);
    }
    // transpose + round weights (loop-invariant)
    k_transpose<<<dim3(3 * HIDD / 32, HIDD / 32), dim3(32, 8)>>>(W_qkv, p_wtq, HIDD, 3 * HIDD);
    k_transpose<<<dim3(HIDD / 32, HIDD / 32), dim3(32, 8)>>>(W_out, p_wto, HIDD, HIDD);

    const long long M1 = 1024 * 1024;  // SSQ*SSQ == SSQ*HIDD

    for (int l = 0; l < NL; l++) {
        // qkv = round(cur) @ round(W_qkv) + b_qkv   (M=8192, N=3072, K=1024)
        k_mma<<<dim3(3 * HIDD / 128, BB * SSQ / 128, 1), 256>>>(
            p_curt, 0, 0, HIDD,
            p_wtq,  0, 0, HIDD,
            p_qkv,  0, 0, 3 * HIDD,
            b_qkv, HIDD);

        // expmap0 scale + tf32 round of q,k in place
        k_scales_apply<<<BB * NH * SSQ * 32 / 256, 256>>>();

        // V^T per head (rounded)
        k_vt<<<dim3(SSQ / 32, HDD / 32, BB * NH), dim3(32, 8)>>>();

        // scores[bh] = qf @ kf^T   (M=N=1024, K=128, batched over 64 bh)
        k_mma<<<dim3(SSQ / 128, SSQ / 128, BB * NH), 256>>>(
            p_qkv,        (long long)SSQ * 3 * HIDD, HDD, 3 * HIDD,
            p_qkv + HIDD, (long long)SSQ * 3 * HIDD, HDD, 3 * HIDD,
            p_scores,     8 * M1, M1, SSQ,
            nullptr, HDD);

        // softmax rows (rounds P to tf32)
        k_softmax<<<BB * NH * SSQ, 256>>>();

        // O[bh] = P @ V   (M=1024, N=128, K=1024)
        k_mma<<<dim3(HDD / 128, SSQ / 128, BB * NH), 256>>>(
            p_scores, 8 * M1, M1, SSQ,
            p_vt,     8LL * HDD * SSQ, (long long)HDD * SSQ, SSQ,
            p_o,      M1, HDD, HIDD,
            nullptr, SSQ);

        // manifold projection + residual (+ refresh rounded shadow)
        k_manifold<<<BB * SSQ, 256>>>(W_pinv, b_pinv,
                                      W_attn + (size_t)l * MDD * HIDD,
                                      b_attn + (size_t)l * HIDD);
    }

    // out = round(cur) @ round(W_out) + b_out   (M=8192, N=1024, K=1024)
    k_mma<<<dim3(HIDD / 128, BB * SSQ / 128, 1), 256>>>(
        p_curt, 0, 0, HIDD,
        p_wto,  0, 0, HIDD,
        out,    0, 0, HIDD,
        b_out, HIDD);
}

// round 10
// speedup vs baseline: 3.2832x; 1.1553x over previous
#include <cuda_runtime.h>
#include <math.h>
#include <stdint.h>

// ---------------- problem constants ----------------
#define BB   8
#define SSQ  1024
#define HIDD 1024
#define NH   8
#define HDD  128
#define MDD  8
#define NL   3
#define EPSS 1e-7f
#define INV_SQRT_D 0.08838834764831845f   // 1/sqrt(128)

// ---------------- scratch (device globals; no cudaMalloc allowed) ----------------
__device__ float g_cur   [BB * SSQ * HIDD];            // fp32 residual stream
__device__ float g_curt  [BB * SSQ * HIDD];            // tf32-rounded shadow of cur
__device__ float g_qkv   [BB * SSQ * 3 * HIDD];        // q,k get scaled+rounded in place
__device__ float g_scores[(size_t)BB * NH * SSQ * SSQ];
__device__ float g_o     [BB * SSQ * HIDD];
__device__ float g_wtq   [3 * HIDD * HIDD];            // W_qkv^T (rounded)
__device__ float g_wto   [HIDD * HIDD];                // W_out^T (rounded)
__device__ float g_vt    [BB * NH * HDD * SSQ];        // V^T per head (rounded)

// ---------------- helpers ----------------
__device__ __forceinline__ uint32_t f2tf(float x) {
    uint32_t u;
    asm("cvt.rna.tf32.f32 %0, %1;" : "=r"(u) : "f"(x));
    return u;
}
__device__ __forceinline__ float f2tff(float x) { return __uint_as_float(f2tf(x)); }

__device__ __forceinline__ void cpa16(uint32_t dst, const float* src) {
    asm volatile("cp.async.cg.shared.global [%0], [%1], 16;\n" :: "r"(dst), "l"(src));
}
__device__ __forceinline__ void cpa_commit(void) {
    asm volatile("cp.async.commit_group;\n");
}

// copy x -> g_cur (exact) and g_curt (tf32-rounded)
__global__ void k_copy_round(const float4* __restrict__ src, float4* __restrict__ dst,
                             float4* __restrict__ dstr, int n4) {
    int i = blockIdx.x * blockDim.x + threadIdx.x;
    if (i >= n4) return;
    float4 v = src[i];
    dst[i] = v;
    float4 r = make_float4(f2tff(v.x), f2tff(v.y), f2tff(v.z), f2tff(v.w));
    dstr[i] = r;
}

// dst[n*K + k] = round(src[k*N + n])
__global__ void k_transpose(const float* __restrict__ src, float* __restrict__ dst, int K, int N) {
    __shared__ float t[32][33];
    int n0 = blockIdx.x * 32, k0 = blockIdx.y * 32;
    int tx = threadIdx.x, ty = threadIdx.y;
#pragma unroll
    for (int j = 0; j < 32; j += 8)
        t[ty + j][tx] = src[(size_t)(k0 + ty + j) * N + n0 + tx];
    __syncthreads();
#pragma unroll
    for (int j = 0; j < 32; j += 8)
        dst[(size_t)(n0 + ty + j) * K + k0 + tx] = f2tff(t[tx][ty + j]);
}

// g_vt[bh][d][s] = round(V[b,s,h,d])
__global__ void k_vt(void) {
    __shared__ float t[32][33];
    int z = blockIdx.z; int b = z >> 3, h = z & 7;
    int s0 = blockIdx.x * 32, d0 = blockIdx.y * 32;
    int tx = threadIdx.x, ty = threadIdx.y;
    const float* src = g_qkv + (size_t)b * SSQ * 3 * HIDD + 2 * HIDD + h * HDD;
#pragma unroll
    for (int j = 0; j < 32; j += 8)
        t[ty + j][tx] = src[(size_t)(s0 + ty + j) * (3 * HIDD) + d0 + tx];
    __syncthreads();
    float* dst = g_vt + (size_t)z * HDD * SSQ;
#pragma unroll
    for (int j = 0; j < 32; j += 8)
        dst[(size_t)(d0 + ty + j) * SSQ + s0 + tx] = f2tff(t[tx][ty + j]);
}

// ---------------- expmap0: scale + round q,k in place ----------------
__global__ void k_scales_apply(void) {
    int gw = (blockIdx.x * blockDim.x + threadIdx.x) >> 5;  // one warp per (b,h,s)
    int lane = threadIdx.x & 31;
    if (gw >= BB * NH * SSQ) return;
    int s = gw & (SSQ - 1);
    int bh = gw >> 10;
    int b = bh >> 3, h = bh & 7;
    float* q = g_qkv + (size_t)(b * SSQ + s) * (3 * HIDD) + h * HDD;
    float* k = q + HIDD;
    float qv[4], kv[4];
    float sq = 0.f, sk = 0.f;
#pragma unroll
    for (int j = 0; j < 4; j++) {
        int d = lane + 32 * j;
        qv[j] = q[d]; sq = fmaf(qv[j], qv[j], sq);
        kv[j] = k[d]; sk = fmaf(kv[j], kv[j], sk);
    }
#pragma unroll
    for (int o = 16; o; o >>= 1) {
        sq += __shfl_xor_sync(0xffffffffu, sq, o);
        sk += __shfl_xor_sync(0xffffffffu, sk, o);
    }
    float nq = fmaxf(sqrtf(sq), EPSS);
    float scq = tanhf(nq) / nq * INV_SQRT_D;
    float nk = fmaxf(sqrtf(sk), EPSS);
    float sck = tanhf(nk) / nk;
#pragma unroll
    for (int j = 0; j < 4; j++) {
        int d = lane + 32 * j;
        q[d] = f2tff(qv[j] * scq);
        k[d] = f2tff(kv[j] * sck);
    }
}

// ---------------- pipelined tf32 tensor-core GEMM ----------------
// C[m,n] = sum_k A[m,k] * B[n,k] (+ bias[n]). All operands pre-rounded tf32 bits.
// Block 128x128, BK=16, 256 threads (8 warps: 2m x 4n, warp tile 64x32).
// 3-stage cp.async pipeline, ONE __syncthreads per chunk.
// SMEM: 48 KB static, zero padding; XOR swizzle: 16B chunk cs of row r stored at
// physical chunk (cs ^ ((r>>1)&3)). Conflict-free for staging and fragment loads.
// z-batch: base += (z/8)*s1 + (z%8)*s2.
#define SROW 16                    // words per row
#define STG_WORDS (128 * SROW)     // 2048 words per operand per stage

__device__ __forceinline__ void load_stage(
    uint32_t* as, uint32_t* bs,
    const float* A, const float* B, int lda, int ldb,
    int m0, int n0, int k0, int rr, int cs, int soff)
{
#pragma unroll
    for (int i = 0; i < 2; i++) {
        int row = rr + i * 64;
        cpa16((uint32_t)__cvta_generic_to_shared(as + (row << 4) + soff),
              A + (size_t)(m0 + row) * lda + k0 + cs * 4);
        cpa16((uint32_t)__cvta_generic_to_shared(bs + (row << 4) + soff),
              B + (size_t)(n0 + row) * ldb + k0 + cs * 4);
    }
    cpa_commit();
}

__global__ __launch_bounds__(256, 2) void k_mma(
    const float* __restrict__ Abase, long long sA1, long long sA2, int lda,
    const float* __restrict__ Bbase, long long sB1, long long sB2, int ldb,
    float*       __restrict__ Cbase, long long sC1, long long sC2, int ldc,
    const float* __restrict__ bias, int K)
{
    __shared__ uint32_t As[3][STG_WORDS];   // 3 stages, 24 KB
    __shared__ uint32_t Bs[3][STG_WORDS];   // 3 stages, 24 KB

    const int z = blockIdx.z;
    const long long zh = z >> 3, zl = z & 7;
    const float* A = Abase + zh * sA1 + zl * sA2;
    const float* B = Bbase + zh * sB1 + zl * sB2;
    float*       C = Cbase + zh * sC1 + zl * sC2;

    const int m0 = blockIdx.y * 128;
    const int n0 = blockIdx.x * 128;
    const int tid = threadIdx.x;
    const int w = tid >> 5, lane = tid & 31;
    const int wm = w & 1, wn = w >> 1;
    const int g = lane >> 2, tg = lane & 3;

    // staging decomposition: row rr (+64), 16B chunk cs, swizzled store offset
    const int rr = tid >> 2;
    const int cs = tid & 3;
    const int soff = ((cs ^ ((rr >> 1) & 3)) << 2);

    // fragment-load swizzled column offsets: co[c] = ((c ^ swz)<<2) + tg
    const int swz = (g >> 1) & 3;
    int co[4];
#pragma unroll
    for (int c = 0; c < 4; c++) co[c] = ((c ^ swz) << 2) + tg;

    float acc[4][4][4];
#pragma unroll
    for (int mi = 0; mi < 4; mi++)
#pragma unroll
        for (int ni = 0; ni < 4; ni++)
#pragma unroll
            for (int r = 0; r < 4; r++) acc[mi][ni][r] = 0.f;

    const int nc = K >> 4;  // K/16 chunks (>= 8 for all call sites)
    load_stage(As[0], Bs[0], A, B, lda, ldb, m0, n0, 0, rr, cs, soff);
    load_stage(As[1], Bs[1], A, B, lda, ldb, m0, n0, 16, rr, cs, soff);

    int st = 0;  // stage of chunk c
    for (int c = 0; c < nc; c++) {
        if (c + 1 < nc) asm volatile("cp.async.wait_group 1;\n");
        else            asm volatile("cp.async.wait_group 0;\n");
        __syncthreads();

        const uint32_t* as = As[st];
        const uint32_t* bs = Bs[st];

#pragma unroll
        for (int kh = 0; kh < 2; kh++) {      // k-halves: cols 0-7 (cs 0,1), 8-15 (cs 2,3)
            const int c0 = co[2 * kh], c1 = co[2 * kh + 1];
            uint32_t af[4][4], bf[4][2];
#pragma unroll
            for (int mi = 0; mi < 4; mi++) {
                int base = (wm * 64 + mi * 16 + g) << 4;
                af[mi][0] = as[base + c0];
                af[mi][1] = as[base + 128 + c0];   // row +8 => +8*16 words
                af[mi][2] = as[base + c1];
                af[mi][3] = as[base + 128 + c1];
            }
#pragma unroll
            for (int ni = 0; ni < 4; ni++) {
                int base = (wn * 32 + ni * 8 + g) << 4;
                bf[ni][0] = bs[base + c0];
                bf[ni][1] = bs[base + c1];
            }
#pragma unroll
            for (int mi = 0; mi < 4; mi++)
#pragma unroll
                for (int ni = 0; ni < 4; ni++) {
                    asm volatile(
                        "mma.sync.aligned.m16n8k8.row.col.f32.tf32.tf32.f32 "
                        "{%0,%1,%2,%3}, {%4,%5,%6,%7}, {%8,%9}, {%0,%1,%2,%3};\n"
                        : "+f"(acc[mi][ni][0]), "+f"(acc[mi][ni][1]),
                          "+f"(acc[mi][ni][2]), "+f"(acc[mi][ni][3])
                        : "r"(af[mi][0]), "r"(af[mi][1]), "r"(af[mi][2]), "r"(af[mi][3]),
                          "r"(bf[ni][0]), "r"(bf[ni][1]));
                }
        }

        // prefetch chunk c+2 into the stage last read at chunk c-1 (all warps are
        // past that read thanks to this iteration's barrier above)
        if (c + 2 < nc) {
            int st2 = st + 2; if (st2 >= 3) st2 -= 3;
            load_stage(As[st2], Bs[st2], A, B, lda, ldb, m0, n0, (c + 2) * 16, rr, cs, soff);
        }
        if (++st == 3) st = 0;
    }

    // epilogue
#pragma unroll
    for (int mi = 0; mi < 4; mi++) {
        int r0 = m0 + wm * 64 + mi * 16 + g;
#pragma unroll
        for (int ni = 0; ni < 4; ni++) {
            int c = n0 + wn * 32 + ni * 8 + 2 * tg;
            float b0 = 0.f, b1 = 0.f;
            if (bias) { b0 = bias[c]; b1 = bias[c + 1]; }
            float2 v;
            v.x = acc[mi][ni][0] + b0; v.y = acc[mi][ni][1] + b1;
            *(float2*)(C + (size_t)r0 * ldc + c) = v;
            v.x = acc[mi][ni][2] + b0; v.y = acc[mi][ni][3] + b1;
            *(float2*)(C + (size_t)(r0 + 8) * ldc + c) = v;
        }
    }
}

// ---------------- row softmax over S=1024 (in place, rounds output to tf32) ----------------
__global__ __launch_bounds__(256) void k_softmax(void) {
    __shared__ float red[256];
    size_t row = blockIdx.x;
    float* p = g_scores + row * SSQ;
    int tid = threadIdx.x;

    float4 v = *(float4*)&p[tid * 4];
    float mx = fmaxf(fmaxf(v.x, v.y), fmaxf(v.z, v.w));
    red[tid] = mx;
    __syncthreads();
#pragma unroll
    for (int s = 128; s > 0; s >>= 1) {
        if (tid < s) red[tid] = fmaxf(red[tid], red[tid + s]);
        __syncthreads();
    }
    mx = red[0];
    __syncthreads();

    v.x = expf(v.x - mx); v.y = expf(v.y - mx);
    v.z = expf(v.z - mx); v.w = expf(v.w - mx);
    red[tid] = v.x + v.y + v.z + v.w;
    __syncthreads();
#pragma unroll
    for (int s = 128; s > 0; s >>= 1) {
        if (tid < s) red[tid] += red[tid + s];
        __syncthreads();
    }
    float inv = 1.f / red[0];
    v.x = f2tff(v.x * inv); v.y = f2tff(v.y * inv);
    v.z = f2tff(v.z * inv); v.w = f2tff(v.w * inv);
    *(float4*)&p[tid * 4] = v;
}

// ---------------- manifold projection + residual update (also refresh rounded shadow) ----------------
__global__ __launch_bounds__(256) void k_manifold(
    const float* __restrict__ Wp, const float* __restrict__ bp,
    const float* __restrict__ Wa, const float* __restrict__ ba)
{
    __shared__ float sO[HIDD];
    __shared__ float sm[MDD];
    const int row = blockIdx.x;
    const int tid = threadIdx.x;

    *(float4*)&sO[tid * 4] = *(const float4*)&g_o[(size_t)row * HIDD + tid * 4];
    __syncthreads();

    const int wid = tid >> 5, lane = tid & 31;
    float part = 0.f;
    for (int i = lane; i < HIDD; i += 32) part = fmaf(sO[i], Wp[i * MDD + wid], part);
#pragma unroll
    for (int o = 16; o; o >>= 1) part += __shfl_xor_sync(0xffffffffu, part, o);
    if (lane == 0) sm[wid] = part + bp[wid];
    __syncthreads();

    const int c = tid * 4;
    float4 u = *(const float4*)&ba[c];
#pragma unroll
    for (int mi = 0; mi < MDD; mi++) {
        float mv = sm[mi];
        float4 w = *(const float4*)&Wa[mi * HIDD + c];
        u.x = fmaf(mv, w.x, u.x);
        u.y = fmaf(mv, w.y, u.y);
        u.z = fmaf(mv, w.z, u.z);
        u.w = fmaf(mv, w.w, u.w);
    }
    size_t off = (size_t)row * HIDD + c;
    float4 cv = *(float4*)&g_cur[off];
    cv.x += u.x; cv.y += u.y; cv.z += u.z; cv.w += u.w;
    *(float4*)&g_cur[off] = cv;
    float4 rv = make_float4(f2tff(cv.x), f2tff(cv.y), f2tff(cv.z), f2tff(cv.w));
    *(float4*)&g_curt[off] = rv;
}

// ---------------- launcher ----------------
extern "C" void kernel_launch(void* const* d_in, const int* in_sizes, int n_in,
                              void* d_out, int out_size) {
    (void)in_sizes; (void)n_in; (void)out_size;
    const float* x      = (const float*)d_in[0];
    const float* W_qkv  = (const float*)d_in[1];
    const float* b_qkv  = (const float*)d_in[2];
    const float* W_pinv = (const float*)d_in[3];
    const float* b_pinv = (const float*)d_in[4];
    const float* W_attn = (const float*)d_in[5];
    const float* b_attn = (const float*)d_in[6];
    const float* W_out  = (const float*)d_in[7];
    const float* b_out  = (const float*)d_in[8];
    float* out = (float*)d_out;

    float *p_cur, *p_curt, *p_qkv, *p_scores, *p_o, *p_wtq, *p_wto, *p_vt;
    cudaGetSymbolAddress((void**)&p_cur, g_cur);
    cudaGetSymbolAddress((void**)&p_curt, g_curt);
    cudaGetSymbolAddress((void**)&p_qkv, g_qkv);
    cudaGetSymbolAddress((void**)&p_scores, g_scores);
    cudaGetSymbolAddress((void**)&p_o, g_o);
    cudaGetSymbolAddress((void**)&p_wtq, g_wtq);
    cudaGetSymbolAddress((void**)&p_wto, g_wto);
    cudaGetSymbolAddress((void**)&p_vt, g_vt);

    // cur = x (exact + rounded shadow)
    {
        int n4 = BB * SSQ * HIDD / 4;
        k_copy_round<<<(n4 + 255) / 256, 256>>>((const float4*)x, (float4*)p_cur,
                                                (float4*)p_curt, n4);
    }
    // transpose + round weights (loop-invariant)
    k_transpose<<<dim3(3 * HIDD / 32, HIDD / 32), dim3(32, 8)>>>(W_qkv, p_wtq, HIDD, 3 * HIDD);
    k_transpose<<<dim3(HIDD / 32, HIDD / 32), dim3(32, 8)>>>(W_out, p_wto, HIDD, HIDD);

    const long long M1 = 1024 * 1024;  // SSQ*SSQ == SSQ*HIDD

    for (int l = 0; l < NL; l++) {
        // qkv = round(cur) @ round(W_qkv) + b_qkv   (M=8192, N=3072, K=1024)
        k_mma<<<dim3(3 * HIDD / 128, BB * SSQ / 128, 1), 256>>>(
            p_curt, 0, 0, HIDD,
            p_wtq,  0, 0, HIDD,
            p_qkv,  0, 0, 3 * HIDD,
            b_qkv, HIDD);

        // expmap0 scale + tf32 round of q,k in place
        k_scales_apply<<<BB * NH * SSQ * 32 / 256, 256>>>();

        // V^T per head (rounded)
        k_vt<<<dim3(SSQ / 32, HDD / 32, BB * NH), dim3(32, 8)>>>();

        // scores[bh] = qf @ kf^T   (M=N=1024, K=128, batched over 64 bh)
        k_mma<<<dim3(SSQ / 128, SSQ / 128, BB * NH), 256>>>(
            p_qkv,        (long long)SSQ * 3 * HIDD, HDD, 3 * HIDD,
            p_qkv + HIDD, (long long)SSQ * 3 * HIDD, HDD, 3 * HIDD,
            p_scores,     8 * M1, M1, SSQ,
            nullptr, HDD);

        // softmax rows (rounds P to tf32)
        k_softmax<<<BB * NH * SSQ, 256>>>();

        // O[bh] = P @ V   (M=1024, N=128, K=1024)
        k_mma<<<dim3(HDD / 128, SSQ / 128, BB * NH), 256>>>(
            p_scores, 8 * M1, M1, SSQ,
            p_vt,     8LL * HDD * SSQ, (long long)HDD * SSQ, SSQ,
            p_o,      M1, HDD, HIDD,
            nullptr, SSQ);

        // manifold projection + residual (+ refresh rounded shadow)
        k_manifold<<<BB * SSQ, 256>>>(W_pinv, b_pinv,
                                      W_attn + (size_t)l * MDD * HIDD,
                                      b_attn + (size_t)l * HIDD);
    }

    // out = round(cur) @ round(W_out) + b_out   (M=8192, N=1024, K=1024)
    k_mma<<<dim3(HIDD / 128, BB * SSQ / 128, 1), 256>>>(
        p_curt, 0, 0, HIDD,
        p_wto,  0, 0, HIDD,
        out,    0, 0, HIDD,
        b_out, HIDD);
}

// round 11
// speedup vs baseline: 3.5241x; 1.0734x over previous
#include <cuda_runtime.h>
#include <math.h>
#include <stdint.h>

// ---------------- problem constants ----------------
#define BB   8
#define SSQ  1024
#define HIDD 1024
#define NH   8
#define HDD  128
#define MDD  8
#define NL   3
#define EPSS 1e-7f
#define INV_SQRT_D 0.08838834764831845f   // 1/sqrt(128)

// ---------------- scratch (device globals; no cudaMalloc allowed) ----------------
__device__ float g_cur   [BB * SSQ * HIDD];            // fp32 residual stream
__device__ float g_curt  [BB * SSQ * HIDD];            // tf32-rounded shadow of cur
__device__ float g_qkv   [BB * SSQ * 3 * HIDD];        // q,k get scaled+rounded in place
__device__ float g_scores[(size_t)BB * NH * SSQ * SSQ];
__device__ float g_o     [BB * SSQ * HIDD];
__device__ float g_wtq   [3 * HIDD * HIDD];            // W_qkv^T (rounded)
__device__ float g_wto   [HIDD * HIDD];                // W_out^T (rounded)
__device__ float g_vt    [BB * NH * HDD * SSQ];        // V^T per head (rounded)

// ---------------- helpers ----------------
__device__ __forceinline__ uint32_t f2tf(float x) {
    uint32_t u;
    asm("cvt.rna.tf32.f32 %0, %1;" : "=r"(u) : "f"(x));
    return u;
}
__device__ __forceinline__ float f2tff(float x) { return __uint_as_float(f2tf(x)); }

__device__ __forceinline__ void cpa16(uint32_t dst, const float* src) {
    asm volatile("cp.async.cg.shared.global [%0], [%1], 16;\n" :: "r"(dst), "l"(src));
}
__device__ __forceinline__ void cpa_commit(void) {
    asm volatile("cp.async.commit_group;\n");
}

#define LDSM4(d0, d1, d2, d3, addr)                                         \
    asm volatile("ldmatrix.sync.aligned.m8n8.x4.shared.b16 {%0,%1,%2,%3}, [%4];" \
                 : "=r"(d0), "=r"(d1), "=r"(d2), "=r"(d3) : "r"(addr))

// copy x -> g_cur (exact) and g_curt (tf32-rounded)
__global__ void k_copy_round(const float4* __restrict__ src, float4* __restrict__ dst,
                             float4* __restrict__ dstr, int n4) {
    int i = blockIdx.x * blockDim.x + threadIdx.x;
    if (i >= n4) return;
    float4 v = src[i];
    dst[i] = v;
    float4 r = make_float4(f2tff(v.x), f2tff(v.y), f2tff(v.z), f2tff(v.w));
    dstr[i] = r;
}

// dst[n*K + k] = round(src[k*N + n])
__global__ void k_transpose(const float* __restrict__ src, float* __restrict__ dst, int K, int N) {
    __shared__ float t[32][33];
    int n0 = blockIdx.x * 32, k0 = blockIdx.y * 32;
    int tx = threadIdx.x, ty = threadIdx.y;
#pragma unroll
    for (int j = 0; j < 32; j += 8)
        t[ty + j][tx] = src[(size_t)(k0 + ty + j) * N + n0 + tx];
    __syncthreads();
#pragma unroll
    for (int j = 0; j < 32; j += 8)
        dst[(size_t)(n0 + ty + j) * K + k0 + tx] = f2tff(t[tx][ty + j]);
}

// g_vt[bh][d][s] = round(V[b,s,h,d])
__global__ void k_vt(void) {
    __shared__ float t[32][33];
    int z = blockIdx.z; int b = z >> 3, h = z & 7;
    int s0 = blockIdx.x * 32, d0 = blockIdx.y * 32;
    int tx = threadIdx.x, ty = threadIdx.y;
    const float* src = g_qkv + (size_t)b * SSQ * 3 * HIDD + 2 * HIDD + h * HDD;
#pragma unroll
    for (int j = 0; j < 32; j += 8)
        t[ty + j][tx] = src[(size_t)(s0 + ty + j) * (3 * HIDD) + d0 + tx];
    __syncthreads();
    float* dst = g_vt + (size_t)z * HDD * SSQ;
#pragma unroll
    for (int j = 0; j < 32; j += 8)
        dst[(size_t)(d0 + ty + j) * SSQ + s0 + tx] = f2tff(t[tx][ty + j]);
}

// ---------------- expmap0: scale + round q,k in place ----------------
__global__ void k_scales_apply(void) {
    int gw = (blockIdx.x * blockDim.x + threadIdx.x) >> 5;  // one warp per (b,h,s)
    int lane = threadIdx.x & 31;
    if (gw >= BB * NH * SSQ) return;
    int s = gw & (SSQ - 1);
    int bh = gw >> 10;
    int b = bh >> 3, h = bh & 7;
    float* q = g_qkv + (size_t)(b * SSQ + s) * (3 * HIDD) + h * HDD;
    float* k = q + HIDD;
    float qv[4], kv[4];
    float sq = 0.f, sk = 0.f;
#pragma unroll
    for (int j = 0; j < 4; j++) {
        int d = lane + 32 * j;
        qv[j] = q[d]; sq = fmaf(qv[j], qv[j], sq);
        kv[j] = k[d]; sk = fmaf(kv[j], kv[j], sk);
    }
#pragma unroll
    for (int o = 16; o; o >>= 1) {
        sq += __shfl_xor_sync(0xffffffffu, sq, o);
        sk += __shfl_xor_sync(0xffffffffu, sk, o);
    }
    float nq = fmaxf(sqrtf(sq), EPSS);
    float scq = tanhf(nq) / nq * INV_SQRT_D;
    float nk = fmaxf(sqrtf(sk), EPSS);
    float sck = tanhf(nk) / nk;
#pragma unroll
    for (int j = 0; j < 4; j++) {
        int d = lane + 32 * j;
        q[d] = f2tff(qv[j] * scq);
        k[d] = f2tff(kv[j] * sck);
    }
}

// ---------------- pipelined tf32 tensor-core GEMM ----------------
// C[m,n] = sum_k A[m,k] * B[n,k] (+ bias[n]). All operands pre-rounded tf32 bits.
// Block 128x128, BK=16, 256 threads (8 warps: 2m x 4n, warp tile 64x32).
// 3-stage cp.async pipeline, ONE __syncthreads per chunk.
// SMEM: 48 KB static, XOR swizzle: 16B chunk cs of row r at physical chunk
// (cs ^ ((r>>1)&3)). Fragments loaded via ldmatrix.m8n8.x4 (b16 word mapping
// == tf32 mma fragment mapping): 12 LDSM/chunk/warp instead of 48 LDS.32.
// z-batch: base += (z/8)*s1 + (z%8)*s2.
#define SROW 16                    // words per row
#define STG_WORDS (128 * SROW)     // 2048 words per operand per stage
#define STG_BYTES (STG_WORDS * 4)  // 8192

__device__ __forceinline__ void load_stage(
    uint32_t* as, uint32_t* bs,
    const float* A, const float* B, int lda, int ldb,
    int m0, int n0, int k0, int rr, int cs, int soff)
{
#pragma unroll
    for (int i = 0; i < 2; i++) {
        int row = rr + i * 64;
        cpa16((uint32_t)__cvta_generic_to_shared(as + (row << 4) + soff),
              A + (size_t)(m0 + row) * lda + k0 + cs * 4);
        cpa16((uint32_t)__cvta_generic_to_shared(bs + (row << 4) + soff),
              B + (size_t)(n0 + row) * ldb + k0 + cs * 4);
    }
    cpa_commit();
}

__global__ __launch_bounds__(256, 2) void k_mma(
    const float* __restrict__ Abase, long long sA1, long long sA2, int lda,
    const float* __restrict__ Bbase, long long sB1, long long sB2, int ldb,
    float*       __restrict__ Cbase, long long sC1, long long sC2, int ldc,
    const float* __restrict__ bias, int K)
{
    __shared__ uint32_t As[3][STG_WORDS];   // 3 stages, 24 KB
    __shared__ uint32_t Bs[3][STG_WORDS];   // 3 stages, 24 KB

    const int z = blockIdx.z;
    const long long zh = z >> 3, zl = z & 7;
    const float* A = Abase + zh * sA1 + zl * sA2;
    const float* B = Bbase + zh * sB1 + zl * sB2;
    float*       C = Cbase + zh * sC1 + zl * sC2;

    const int m0 = blockIdx.y * 128;
    const int n0 = blockIdx.x * 128;
    const int tid = threadIdx.x;
    const int w = tid >> 5, lane = tid & 31;
    const int wm = w & 1, wn = w >> 1;
    const int g = lane >> 2, tg = lane & 3;

    // staging decomposition: row rr (+64), 16B chunk cs, swizzled store offset
    const int rr = tid >> 2;
    const int cs = tid & 3;
    const int soff = ((cs ^ ((rr >> 1) & 3)) << 2);

    // ---- ldmatrix per-lane byte addresses (within stage 0; kh=1 => addr^32) ----
    // A fragment for mi: tiles {rows+0 cs0, rows+8 cs0, rows+0 cs1, rows+8 cs1}
    // B pair p (ni=2p,2p+1): tiles {ni rows cs0, ni rows cs1, ni+1 rows cs0, ni+1 rows cs1}
    const int lt = lane >> 3, lr = lane & 7;   // tile index, row-in-tile
    const uint32_t asBase = (uint32_t)__cvta_generic_to_shared(&As[0][0]);
    const uint32_t bsBase = (uint32_t)__cvta_generic_to_shared(&Bs[0][0]);
    uint32_t aAddr[4], bAddr[2];
#pragma unroll
    for (int mi = 0; mi < 4; mi++) {
        int r = wm * 64 + mi * 16 + (lt & 1) * 8 + lr;
        int csb = lt >> 1;
        aAddr[mi] = asBase + (uint32_t)(r * 64 + ((csb ^ ((r >> 1) & 3)) << 4));
    }
#pragma unroll
    for (int p = 0; p < 2; p++) {
        int r = wn * 32 + p * 16 + (lt >> 1) * 8 + lr;
        int csb = lt & 1;
        bAddr[p] = bsBase + (uint32_t)(r * 64 + ((csb ^ ((r >> 1) & 3)) << 4));
    }

    float acc[4][4][4];
#pragma unroll
    for (int mi = 0; mi < 4; mi++)
#pragma unroll
        for (int ni = 0; ni < 4; ni++)
#pragma unroll
            for (int r = 0; r < 4; r++) acc[mi][ni][r] = 0.f;

    const int nc = K >> 4;  // K/16 chunks (>= 8 for all call sites)
    load_stage(As[0], Bs[0], A, B, lda, ldb, m0, n0, 0, rr, cs, soff);
    load_stage(As[1], Bs[1], A, B, lda, ldb, m0, n0, 16, rr, cs, soff);

    int st = 0;  // stage of chunk c
    for (int c = 0; c < nc; c++) {
        if (c + 1 < nc) asm volatile("cp.async.wait_group 1;\n");
        else            asm volatile("cp.async.wait_group 0;\n");
        __syncthreads();

        const uint32_t sb = (uint32_t)(st * STG_BYTES);

#pragma unroll
        for (int kh = 0; kh < 2; kh++) {
            const uint32_t kx = sb ^ (kh << 5);
            uint32_t af[4][4], bf[2][4];
#pragma unroll
            for (int mi = 0; mi < 4; mi++)
                LDSM4(af[mi][0], af[mi][1], af[mi][2], af[mi][3], aAddr[mi] + sb ^ 0u + (kh << 5));
#pragma unroll
            for (int p = 0; p < 2; p++)
                LDSM4(bf[p][0], bf[p][1], bf[p][2], bf[p][3], bAddr[p] + sb ^ 0u + (kh << 5));
            (void)kx;
#pragma unroll
            for (int mi = 0; mi < 4; mi++)
#pragma unroll
                for (int ni = 0; ni < 4; ni++) {
                    const uint32_t b0 = bf[ni >> 1][(ni & 1) * 2];
                    const uint32_t b1 = bf[ni >> 1][(ni & 1) * 2 + 1];
                    asm volatile(
                        "mma.sync.aligned.m16n8k8.row.col.f32.tf32.tf32.f32 "
                        "{%0,%1,%2,%3}, {%4,%5,%6,%7}, {%8,%9}, {%0,%1,%2,%3};\n"
                        : "+f"(acc[mi][ni][0]), "+f"(acc[mi][ni][1]),
                          "+f"(acc[mi][ni][2]), "+f"(acc[mi][ni][3])
                        : "r"(af[mi][0]), "r"(af[mi][1]), "r"(af[mi][2]), "r"(af[mi][3]),
                          "r"(b0), "r"(b1));
                }
        }

        // prefetch chunk c+2 into the stage last read at chunk c-1
        if (c + 2 < nc) {
            int st2 = st + 2; if (st2 >= 3) st2 -= 3;
            load_stage(As[st2], Bs[st2], A, B, lda, ldb, m0, n0, (c + 2) * 16, rr, cs, soff);
        }
        if (++st == 3) st = 0;
    }

    // epilogue
#pragma unroll
    for (int mi = 0; mi < 4; mi++) {
        int r0 = m0 + wm * 64 + mi * 16 + g;
#pragma unroll
        for (int ni = 0; ni < 4; ni++) {
            int c = n0 + wn * 32 + ni * 8 + 2 * tg;
            float b0 = 0.f, b1 = 0.f;
            if (bias) { b0 = bias[c]; b1 = bias[c + 1]; }
            float2 v;
            v.x = acc[mi][ni][0] + b0; v.y = acc[mi][ni][1] + b1;
            *(float2*)(C + (size_t)r0 * ldc + c) = v;
            v.x = acc[mi][ni][2] + b0; v.y = acc[mi][ni][3] + b1;
            *(float2*)(C + (size_t)(r0 + 8) * ldc + c) = v;
        }
    }
}

// ---------------- row softmax over S=1024 (in place, rounds output to tf32) ----------------
__global__ __launch_bounds__(256) void k_softmax(void) {
    __shared__ float red[256];
    size_t row = blockIdx.x;
    float* p = g_scores + row * SSQ;
    int tid = threadIdx.x;

    float4 v = *(float4*)&p[tid * 4];
    float mx = fmaxf(fmaxf(v.x, v.y), fmaxf(v.z, v.w));
    red[tid] = mx;
    __syncthreads();
#pragma unroll
    for (int s = 128; s > 0; s >>= 1) {
        if (tid < s) red[tid] = fmaxf(red[tid], red[tid + s]);
        __syncthreads();
    }
    mx = red[0];
    __syncthreads();

    v.x = expf(v.x - mx); v.y = expf(v.y - mx);
    v.z = expf(v.z - mx); v.w = expf(v.w - mx);
    red[tid] = v.x + v.y + v.z + v.w;
    __syncthreads();
#pragma unroll
    for (int s = 128; s > 0; s >>= 1) {
        if (tid < s) red[tid] += red[tid + s];
        __syncthreads();
    }
    float inv = 1.f / red[0];
    v.x = f2tff(v.x * inv); v.y = f2tff(v.y * inv);
    v.z = f2tff(v.z * inv); v.w = f2tff(v.w * inv);
    *(float4*)&p[tid * 4] = v;
}

// ---------------- manifold projection + residual update (also refresh rounded shadow) ----------------
__global__ __launch_bounds__(256) void k_manifold(
    const float* __restrict__ Wp, const float* __restrict__ bp,
    const float* __restrict__ Wa, const float* __restrict__ ba)
{
    __shared__ float sO[HIDD];
    __shared__ float sm[MDD];
    const int row = blockIdx.x;
    const int tid = threadIdx.x;

    *(float4*)&sO[tid * 4] = *(const float4*)&g_o[(size_t)row * HIDD + tid * 4];
    __syncthreads();

    const int wid = tid >> 5, lane = tid & 31;
    float part = 0.f;
    for (int i = lane; i < HIDD; i += 32) part = fmaf(sO[i], Wp[i * MDD + wid], part);
#pragma unroll
    for (int o = 16; o; o >>= 1) part += __shfl_xor_sync(0xffffffffu, part, o);
    if (lane == 0) sm[wid] = part + bp[wid];
    __syncthreads();

    const int c = tid * 4;
    float4 u = *(const float4*)&ba[c];
#pragma unroll
    for (int mi = 0; mi < MDD; mi++) {
        float mv = sm[mi];
        float4 w = *(const float4*)&Wa[mi * HIDD + c];
        u.x = fmaf(mv, w.x, u.x);
        u.y = fmaf(mv, w.y, u.y);
        u.z = fmaf(mv, w.z, u.z);
        u.w = fmaf(mv, w.w, u.w);
    }
    size_t off = (size_t)row * HIDD + c;
    float4 cv = *(float4*)&g_cur[off];
    cv.x += u.x; cv.y += u.y; cv.z += u.z; cv.w += u.w;
    *(float4*)&g_cur[off] = cv;
    float4 rv = make_float4(f2tff(cv.x), f2tff(cv.y), f2tff(cv.z), f2tff(cv.w));
    *(float4*)&g_curt[off] = rv;
}

// ---------------- launcher ----------------
extern "C" void kernel_launch(void* const* d_in, const int* in_sizes, int n_in,
                              void* d_out, int out_size) {
    (void)in_sizes; (void)n_in; (void)out_size;
    const float* x      = (const float*)d_in[0];
    const float* W_qkv  = (const float*)d_in[1];
    const float* b_qkv  = (const float*)d_in[2];
    const float* W_pinv = (const float*)d_in[3];
    const float* b_pinv = (const float*)d_in[4];
    const float* W_attn = (const float*)d_in[5];
    const float* b_attn = (const float*)d_in[6];
    const float* W_out  = (const float*)d_in[7];
    const float* b_out  = (const float*)d_in[8];
    float* out = (float*)d_out;

    float *p_cur, *p_curt, *p_qkv, *p_scores, *p_o, *p_wtq, *p_wto, *p_vt;
    cudaGetSymbolAddress((void**)&p_cur, g_cur);
    cudaGetSymbolAddress((void**)&p_curt, g_curt);
    cudaGetSymbolAddress((void**)&p_qkv, g_qkv);
    cudaGetSymbolAddress((void**)&p_scores, g_scores);
    cudaGetSymbolAddress((void**)&p_o, g_o);
    cudaGetSymbolAddress((void**)&p_wtq, g_wtq);
    cudaGetSymbolAddress((void**)&p_wto, g_wto);
    cudaGetSymbolAddress((void**)&p_vt, g_vt);

    // cur = x (exact + rounded shadow)
    {
        int n4 = BB * SSQ * HIDD / 4;
        k_copy_round<<<(n4 + 255) / 256, 256>>>((const float4*)x, (float4*)p_cur,
                                                (float4*)p_curt, n4);
    }
    // transpose + round weights (loop-invariant)
    k_transpose<<<dim3(3 * HIDD / 32, HIDD / 32), dim3(32, 8)>>>(W_qkv, p_wtq, HIDD, 3 * HIDD);
    k_transpose<<<dim3(HIDD / 32, HIDD / 32), dim3(32, 8)>>>(W_out, p_wto, HIDD, HIDD);

    const long long M1 = 1024 * 1024;  // SSQ*SSQ == SSQ*HIDD

    for (int l = 0; l < NL; l++) {
        // qkv = round(cur) @ round(W_qkv) + b_qkv   (M=8192, N=3072, K=1024)
        k_mma<<<dim3(3 * HIDD / 128, BB * SSQ / 128, 1), 256>>>(
            p_curt, 0, 0, HIDD,
            p_wtq,  0, 0, HIDD,
            p_qkv,  0, 0, 3 * HIDD,
            b_qkv, HIDD);

        // expmap0 scale + tf32 round of q,k in place
        k_scales_apply<<<BB * NH * SSQ * 32 / 256, 256>>>();

        // V^T per head (rounded)
        k_vt<<<dim3(SSQ / 32, HDD / 32, BB * NH), dim3(32, 8)>>>();

        // scores[bh] = qf @ kf^T   (M=N=1024, K=128, batched over 64 bh)
        k_mma<<<dim3(SSQ / 128, SSQ / 128, BB * NH), 256>>>(
            p_qkv,        (long long)SSQ * 3 * HIDD, HDD, 3 * HIDD,
            p_qkv + HIDD, (long long)SSQ * 3 * HIDD, HDD, 3 * HIDD,
            p_scores,     8 * M1, M1, SSQ,
            nullptr, HDD);

        // softmax rows (rounds P to tf32)
        k_softmax<<<BB * NH * SSQ, 256>>>();

        // O[bh] = P @ V   (M=1024, N=128, K=1024)
        k_mma<<<dim3(HDD / 128, SSQ / 128, BB * NH), 256>>>(
            p_scores, 8 * M1, M1, SSQ,
            p_vt,     8LL * HDD * SSQ, (long long)HDD * SSQ, SSQ,
            p_o,      M1, HDD, HIDD,
            nullptr, SSQ);

        // manifold projection + residual (+ refresh rounded shadow)
        k_manifold<<<BB * SSQ, 256>>>(W_pinv, b_pinv,
                                      W_attn + (size_t)l * MDD * HIDD,
                                      b_attn + (size_t)l * HIDD);
    }

    // out = round(cur) @ round(W_out) + b_out   (M=8192, N=1024, K=1024)
    k_mma<<<dim3(HIDD / 128, BB * SSQ / 128, 1), 256>>>(
        p_curt, 0, 0, HIDD,
        p_wto,  0, 0, HIDD,
        out,    0, 0, HIDD,
        b_out, HIDD);
}

// round 12
// speedup vs baseline: 3.7501x; 1.0641x over previous
#include <cuda_runtime.h>
#include <math.h>
#include <stdint.h>

// ---------------- problem constants ----------------
#define BB   8
#define SSQ  1024
#define HIDD 1024
#define NH   8
#define HDD  128
#define MDD  8
#define NL   3
#define EPSS 1e-7f
#define INV_SQRT_D 0.08838834764831845f   // 1/sqrt(128)

// ---------------- scratch (device globals; no cudaMalloc allowed) ----------------
__device__ float g_cur   [BB * SSQ * HIDD];            // fp32 residual stream
__device__ float g_curt  [BB * SSQ * HIDD];            // tf32-rounded shadow of cur
__device__ float g_qkv   [BB * SSQ * 3 * HIDD];        // q,k get scaled+rounded in place
__device__ float g_scores[(size_t)BB * NH * SSQ * SSQ];
__device__ float g_o     [BB * SSQ * HIDD];
__device__ float g_wtq   [3 * HIDD * HIDD];            // W_qkv^T (rounded)
__device__ float g_wto   [HIDD * HIDD];                // W_out^T (rounded)
__device__ float g_vt    [BB * NH * HDD * SSQ];        // V^T per head (rounded)

// ---------------- helpers ----------------
__device__ __forceinline__ uint32_t f2tf(float x) {
    uint32_t u;
    asm("cvt.rna.tf32.f32 %0, %1;" : "=r"(u) : "f"(x));
    return u;
}
__device__ __forceinline__ float f2tff(float x) { return __uint_as_float(f2tf(x)); }

__device__ __forceinline__ void cpa16(uint32_t dst, const float* src) {
    asm volatile("cp.async.cg.shared.global [%0], [%1], 16;\n" :: "r"(dst), "l"(src));
}
__device__ __forceinline__ void cpa_commit(void) {
    asm volatile("cp.async.commit_group;\n");
}

#define LDSM4(d0, d1, d2, d3, addr)                                         \
    asm volatile("ldmatrix.sync.aligned.m8n8.x4.shared.b16 {%0,%1,%2,%3}, [%4];" \
                 : "=r"(d0), "=r"(d1), "=r"(d2), "=r"(d3) : "r"(addr))

// copy x -> g_cur (exact) and g_curt (tf32-rounded)
__global__ void k_copy_round(const float4* __restrict__ src, float4* __restrict__ dst,
                             float4* __restrict__ dstr, int n4) {
    int i = blockIdx.x * blockDim.x + threadIdx.x;
    if (i >= n4) return;
    float4 v = src[i];
    dst[i] = v;
    float4 r = make_float4(f2tff(v.x), f2tff(v.y), f2tff(v.z), f2tff(v.w));
    dstr[i] = r;
}

// dst[n*K + k] = round(src[k*N + n])
__global__ void k_transpose(const float* __restrict__ src, float* __restrict__ dst, int K, int N) {
    __shared__ float t[32][33];
    int n0 = blockIdx.x * 32, k0 = blockIdx.y * 32;
    int tx = threadIdx.x, ty = threadIdx.y;
#pragma unroll
    for (int j = 0; j < 32; j += 8)
        t[ty + j][tx] = src[(size_t)(k0 + ty + j) * N + n0 + tx];
    __syncthreads();
#pragma unroll
    for (int j = 0; j < 32; j += 8)
        dst[(size_t)(n0 + ty + j) * K + k0 + tx] = f2tff(t[tx][ty + j]);
}

// g_vt[bh][d][s] = round(V[b,s,h,d])
__global__ void k_vt(void) {
    __shared__ float t[32][33];
    int z = blockIdx.z; int b = z >> 3, h = z & 7;
    int s0 = blockIdx.x * 32, d0 = blockIdx.y * 32;
    int tx = threadIdx.x, ty = threadIdx.y;
    const float* src = g_qkv + (size_t)b * SSQ * 3 * HIDD + 2 * HIDD + h * HDD;
#pragma unroll
    for (int j = 0; j < 32; j += 8)
        t[ty + j][tx] = src[(size_t)(s0 + ty + j) * (3 * HIDD) + d0 + tx];
    __syncthreads();
    float* dst = g_vt + (size_t)z * HDD * SSQ;
#pragma unroll
    for (int j = 0; j < 32; j += 8)
        dst[(size_t)(d0 + ty + j) * SSQ + s0 + tx] = f2tff(t[tx][ty + j]);
}

// ---------------- expmap0: scale + round q,k in place ----------------
__global__ void k_scales_apply(void) {
    int gw = (blockIdx.x * blockDim.x + threadIdx.x) >> 5;  // one warp per (b,h,s)
    int lane = threadIdx.x & 31;
    if (gw >= BB * NH * SSQ) return;
    int s = gw & (SSQ - 1);
    int bh = gw >> 10;
    int b = bh >> 3, h = bh & 7;
    float* q = g_qkv + (size_t)(b * SSQ + s) * (3 * HIDD) + h * HDD;
    float* k = q + HIDD;
    float qv[4], kv[4];
    float sq = 0.f, sk = 0.f;
#pragma unroll
    for (int j = 0; j < 4; j++) {
        int d = lane + 32 * j;
        qv[j] = q[d]; sq = fmaf(qv[j], qv[j], sq);
        kv[j] = k[d]; sk = fmaf(kv[j], kv[j], sk);
    }
#pragma unroll
    for (int o = 16; o; o >>= 1) {
        sq += __shfl_xor_sync(0xffffffffu, sq, o);
        sk += __shfl_xor_sync(0xffffffffu, sk, o);
    }
    float nq = fmaxf(sqrtf(sq), EPSS);
    float scq = tanhf(nq) / nq * INV_SQRT_D;
    float nk = fmaxf(sqrtf(sk), EPSS);
    float sck = tanhf(nk) / nk;
#pragma unroll
    for (int j = 0; j < 4; j++) {
        int d = lane + 32 * j;
        q[d] = f2tff(qv[j] * scq);
        k[d] = f2tff(kv[j] * sck);
    }
}

// ---------------- pipelined tf32 tensor-core GEMM ----------------
// C[m,n] = sum_k A[m,k] * B[n,k] (+ bias[n]). All operands pre-rounded tf32 bits.
// Block 128x128, BK=16, 256 threads (8 warps: 2m x 4n, warp tile 64x32).
// 3-stage cp.async pipeline; prefetch for chunk c+2 issued at the TOP of chunk c
// (right after the barrier), maximizing load/MMA overlap.
// SMEM: 48 KB static, XOR swizzle: 16B chunk cs of row r at physical chunk
// (cs ^ ((r>>1)&3)). Fragments via ldmatrix.m8n8.x4 (b16 word map == tf32 frag map).
// z-batch: base += (z/8)*s1 + (z%8)*s2.
#define SROW 16                    // words per row
#define STG_WORDS (128 * SROW)     // 2048 words per operand per stage
#define STG_BYTES (STG_WORDS * 4)  // 8192

__global__ __launch_bounds__(256, 2) void k_mma(
    const float* __restrict__ Abase, long long sA1, long long sA2, int lda,
    const float* __restrict__ Bbase, long long sB1, long long sB2, int ldb,
    float*       __restrict__ Cbase, long long sC1, long long sC2, int ldc,
    const float* __restrict__ bias, int K)
{
    __shared__ uint32_t As[3][STG_WORDS];   // 3 stages, 24 KB
    __shared__ uint32_t Bs[3][STG_WORDS];   // 3 stages, 24 KB

    const int z = blockIdx.z;
    const long long zh = z >> 3, zl = z & 7;
    const float* A = Abase + zh * sA1 + zl * sA2;
    const float* B = Bbase + zh * sB1 + zl * sB2;
    float*       C = Cbase + zh * sC1 + zl * sC2;

    const int m0 = blockIdx.y * 128;
    const int n0 = blockIdx.x * 128;
    const int tid = threadIdx.x;
    const int w = tid >> 5, lane = tid & 31;
    const int wm = w & 1, wn = w >> 1;
    const int g = lane >> 2, tg = lane & 3;

    // staging decomposition: rows rr, rr+64; 16B chunk cs; swizzled word offset
    const int rr = tid >> 2;
    const int cs = tid & 3;
    const int soff = ((cs ^ ((rr >> 1) & 3)) << 2);
    const uint32_t aoff0 = (uint32_t)((((rr)      << 4) + soff) << 2);  // byte offsets
    const uint32_t aoff1 = (uint32_t)((((rr + 64) << 4) + soff) << 2);
    const uint32_t asB = (uint32_t)__cvta_generic_to_shared(&As[0][0]);
    const uint32_t bsB = (uint32_t)__cvta_generic_to_shared(&Bs[0][0]);

    // running global pointers (advance +16 floats per issued stage)
    const float* pa0 = A + (size_t)(m0 + rr) * lda + cs * 4;
    const float* pa1 = pa0 + (size_t)64 * lda;
    const float* pb0 = B + (size_t)(n0 + rr) * ldb + cs * 4;
    const float* pb1 = pb0 + (size_t)64 * ldb;

#define ISSUE_STAGE(stIdx)                                                     \
    {                                                                          \
        uint32_t as_ = asB + (uint32_t)(stIdx) * STG_BYTES;                    \
        uint32_t bs_ = bsB + (uint32_t)(stIdx) * STG_BYTES;                    \
        cpa16(as_ + aoff0, pa0); cpa16(bs_ + aoff0, pb0);                      \
        cpa16(as_ + aoff1, pa1); cpa16(bs_ + aoff1, pb1);                      \
        cpa_commit();                                                          \
        pa0 += 16; pa1 += 16; pb0 += 16; pb1 += 16;                            \
    }

    // ---- ldmatrix per-lane byte addresses (stage 0; stage => +st*8K; kh=1 => ^32) ----
    const int lt = lane >> 3, lr = lane & 7;   // tile index, row-in-tile
    uint32_t aAddr[4], bAddr[2];
#pragma unroll
    for (int mi = 0; mi < 4; mi++) {
        int r = wm * 64 + mi * 16 + (lt & 1) * 8 + lr;
        int csb = lt >> 1;
        aAddr[mi] = asB + (uint32_t)(r * 64 + ((csb ^ ((r >> 1) & 3)) << 4));
    }
#pragma unroll
    for (int p = 0; p < 2; p++) {
        int r = wn * 32 + p * 16 + (lt >> 1) * 8 + lr;
        int csb = lt & 1;
        bAddr[p] = bsB + (uint32_t)(r * 64 + ((csb ^ ((r >> 1) & 3)) << 4));
    }

    float acc[4][4][4];
#pragma unroll
    for (int mi = 0; mi < 4; mi++)
#pragma unroll
        for (int ni = 0; ni < 4; ni++)
#pragma unroll
            for (int r = 0; r < 4; r++) acc[mi][ni][r] = 0.f;

    const int nc = K >> 4;  // K/16 chunks (>= 8 for all call sites)
    ISSUE_STAGE(0);
    ISSUE_STAGE(1);

    int st = 0;  // stage of chunk c
    for (int c = 0; c < nc; c++) {
        if (c + 1 < nc) asm volatile("cp.async.wait_group 1;\n");
        else            asm volatile("cp.async.wait_group 0;\n");
        __syncthreads();

        // early prefetch: target stage (st+2)%3 was last read at chunk c-1,
        // which the barrier above has already fenced.
        if (c + 2 < nc) {
            int st2 = st + 2; if (st2 >= 3) st2 -= 3;
            ISSUE_STAGE(st2);
        }

        const uint32_t sb = (uint32_t)st * STG_BYTES;
        uint32_t aC[4], bC[2];
#pragma unroll
        for (int mi = 0; mi < 4; mi++) aC[mi] = aAddr[mi] + sb;
#pragma unroll
        for (int p = 0; p < 2; p++)   bC[p]  = bAddr[p] + sb;

#pragma unroll
        for (int kh = 0; kh < 2; kh++) {
            const uint32_t kx = (uint32_t)(kh << 5);
            uint32_t af[4][4], bf[2][4];
#pragma unroll
            for (int mi = 0; mi < 4; mi++)
                LDSM4(af[mi][0], af[mi][1], af[mi][2], af[mi][3], aC[mi] ^ kx);
#pragma unroll
            for (int p = 0; p < 2; p++)
                LDSM4(bf[p][0], bf[p][1], bf[p][2], bf[p][3], bC[p] ^ kx);
#pragma unroll
            for (int mi = 0; mi < 4; mi++)
#pragma unroll
                for (int ni = 0; ni < 4; ni++) {
                    const uint32_t b0 = bf[ni >> 1][(ni & 1) * 2];
                    const uint32_t b1 = bf[ni >> 1][(ni & 1) * 2 + 1];
                    asm volatile(
                        "mma.sync.aligned.m16n8k8.row.col.f32.tf32.tf32.f32 "
                        "{%0,%1,%2,%3}, {%4,%5,%6,%7}, {%8,%9}, {%0,%1,%2,%3};\n"
                        : "+f"(acc[mi][ni][0]), "+f"(acc[mi][ni][1]),
                          "+f"(acc[mi][ni][2]), "+f"(acc[mi][ni][3])
                        : "r"(af[mi][0]), "r"(af[mi][1]), "r"(af[mi][2]), "r"(af[mi][3]),
                          "r"(b0), "r"(b1));
                }
        }
        if (++st == 3) st = 0;
    }
#undef ISSUE_STAGE

    // epilogue
#pragma unroll
    for (int mi = 0; mi < 4; mi++) {
        int r0 = m0 + wm * 64 + mi * 16 + g;
#pragma unroll
        for (int ni = 0; ni < 4; ni++) {
            int c = n0 + wn * 32 + ni * 8 + 2 * tg;
            float b0 = 0.f, b1 = 0.f;
            if (bias) { b0 = bias[c]; b1 = bias[c + 1]; }
            float2 v;
            v.x = acc[mi][ni][0] + b0; v.y = acc[mi][ni][1] + b1;
            *(float2*)(C + (size_t)r0 * ldc + c) = v;
            v.x = acc[mi][ni][2] + b0; v.y = acc[mi][ni][3] + b1;
            *(float2*)(C + (size_t)(r0 + 8) * ldc + c) = v;
        }
    }
}

// ---------------- row softmax over S=1024: warp per row, no barriers ----------------
__global__ __launch_bounds__(256) void k_softmax(void) {
    const int wid = threadIdx.x >> 5, lane = threadIdx.x & 31;
    const size_t row = (size_t)blockIdx.x * 8 + wid;
    float* p = g_scores + row * SSQ;

    float4 v[8];
    float mx = -1e30f;
#pragma unroll
    for (int j = 0; j < 8; j++) {
        v[j] = *(float4*)&p[(lane + j * 32) * 4];
        mx = fmaxf(mx, fmaxf(fmaxf(v[j].x, v[j].y), fmaxf(v[j].z, v[j].w)));
    }
#pragma unroll
    for (int o = 16; o; o >>= 1) mx = fmaxf(mx, __shfl_xor_sync(0xffffffffu, mx, o));

    float sum = 0.f;
#pragma unroll
    for (int j = 0; j < 8; j++) {
        v[j].x = expf(v[j].x - mx); v[j].y = expf(v[j].y - mx);
        v[j].z = expf(v[j].z - mx); v[j].w = expf(v[j].w - mx);
        sum += (v[j].x + v[j].y) + (v[j].z + v[j].w);
    }
#pragma unroll
    for (int o = 16; o; o >>= 1) sum += __shfl_xor_sync(0xffffffffu, sum, o);

    float inv = 1.f / sum;
#pragma unroll
    for (int j = 0; j < 8; j++) {
        float4 r;
        r.x = f2tff(v[j].x * inv); r.y = f2tff(v[j].y * inv);
        r.z = f2tff(v[j].z * inv); r.w = f2tff(v[j].w * inv);
        *(float4*)&p[(lane + j * 32) * 4] = r;
    }
}

// ---------------- manifold projection + residual update (also refresh rounded shadow) ----------------
__global__ __launch_bounds__(256) void k_manifold(
    const float* __restrict__ Wp, const float* __restrict__ bp,
    const float* __restrict__ Wa, const float* __restrict__ ba)
{
    __shared__ float sO[HIDD];
    __shared__ float sm[MDD];
    const int row = blockIdx.x;
    const int tid = threadIdx.x;

    *(float4*)&sO[tid * 4] = *(const float4*)&g_o[(size_t)row * HIDD + tid * 4];
    __syncthreads();

    const int wid = tid >> 5, lane = tid & 31;
    float part = 0.f;
    for (int i = lane; i < HIDD; i += 32) part = fmaf(sO[i], Wp[i * MDD + wid], part);
#pragma unroll
    for (int o = 16; o; o >>= 1) part += __shfl_xor_sync(0xffffffffu, part, o);
    if (lane == 0) sm[wid] = part + bp[wid];
    __syncthreads();

    const int c = tid * 4;
    float4 u = *(const float4*)&ba[c];
#pragma unroll
    for (int mi = 0; mi < MDD; mi++) {
        float mv = sm[mi];
        float4 w = *(const float4*)&Wa[mi * HIDD + c];
        u.x = fmaf(mv, w.x, u.x);
        u.y = fmaf(mv, w.y, u.y);
        u.z = fmaf(mv, w.z, u.z);
        u.w = fmaf(mv, w.w, u.w);
    }
    size_t off = (size_t)row * HIDD + c;
    float4 cv = *(float4*)&g_cur[off];
    cv.x += u.x; cv.y += u.y; cv.z += u.z; cv.w += u.w;
    *(float4*)&g_cur[off] = cv;
    float4 rv = make_float4(f2tff(cv.x), f2tff(cv.y), f2tff(cv.z), f2tff(cv.w));
    *(float4*)&g_curt[off] = rv;
}

// ---------------- launcher ----------------
extern "C" void kernel_launch(void* const* d_in, const int* in_sizes, int n_in,
                              void* d_out, int out_size) {
    (void)in_sizes; (void)n_in; (void)out_size;
    const float* x      = (const float*)d_in[0];
    const float* W_qkv  = (const float*)d_in[1];
    const float* b_qkv  = (const float*)d_in[2];
    const float* W_pinv = (const float*)d_in[3];
    const float* b_pinv = (const float*)d_in[4];
    const float* W_attn = (const float*)d_in[5];
    const float* b_attn = (const float*)d_in[6];
    const float* W_out  = (const float*)d_in[7];
    const float* b_out  = (const float*)d_in[8];
    float* out = (float*)d_out;

    float *p_cur, *p_curt, *p_qkv, *p_scores, *p_o, *p_wtq, *p_wto, *p_vt;
    cudaGetSymbolAddress((void**)&p_cur, g_cur);
    cudaGetSymbolAddress((void**)&p_curt, g_curt);
    cudaGetSymbolAddress((void**)&p_qkv, g_qkv);
    cudaGetSymbolAddress((void**)&p_scores, g_scores);
    cudaGetSymbolAddress((void**)&p_o, g_o);
    cudaGetSymbolAddress((void**)&p_wtq, g_wtq);
    cudaGetSymbolAddress((void**)&p_wto, g_wto);
    cudaGetSymbolAddress((void**)&p_vt, g_vt);

    // cur = x (exact + rounded shadow)
    {
        int n4 = BB * SSQ * HIDD / 4;
        k_copy_round<<<(n4 + 255) / 256, 256>>>((const float4*)x, (float4*)p_cur,
                                                (float4*)p_curt, n4);
    }
    // transpose + round weights (loop-invariant)
    k_transpose<<<dim3(3 * HIDD / 32, HIDD / 32), dim3(32, 8)>>>(W_qkv, p_wtq, HIDD, 3 * HIDD);
    k_transpose<<<dim3(HIDD / 32, HIDD / 32), dim3(32, 8)>>>(W_out, p_wto, HIDD, HIDD);

    const long long M1 = 1024 * 1024;  // SSQ*SSQ == SSQ*HIDD

    for (int l = 0; l < NL; l++) {
        // qkv = round(cur) @ round(W_qkv) + b_qkv   (M=8192, N=3072, K=1024)
        k_mma<<<dim3(3 * HIDD / 128, BB * SSQ / 128, 1), 256>>>(
            p_curt, 0, 0, HIDD,
            p_wtq,  0, 0, HIDD,
            p_qkv,  0, 0, 3 * HIDD,
            b_qkv, HIDD);

        // expmap0 scale + tf32 round of q,k in place
        k_scales_apply<<<BB * NH * SSQ * 32 / 256, 256>>>();

        // V^T per head (rounded)
        k_vt<<<dim3(SSQ / 32, HDD / 32, BB * NH), dim3(32, 8)>>>();

        // scores[bh] = qf @ kf^T   (M=N=1024, K=128, batched over 64 bh)
        k_mma<<<dim3(SSQ / 128, SSQ / 128, BB * NH), 256>>>(
            p_qkv,        (long long)SSQ * 3 * HIDD, HDD, 3 * HIDD,
            p_qkv + HIDD, (long long)SSQ * 3 * HIDD, HDD, 3 * HIDD,
            p_scores,     8 * M1, M1, SSQ,
            nullptr, HDD);

        // softmax rows (rounds P to tf32): warp per row, 8 rows/block
        k_softmax<<<BB * NH * SSQ / 8, 256>>>();

        // O[bh] = P @ V   (M=1024, N=128, K=1024)
        k_mma<<<dim3(HDD / 128, SSQ / 128, BB * NH), 256>>>(
            p_scores, 8 * M1, M1, SSQ,
            p_vt,     8LL * HDD * SSQ, (long long)HDD * SSQ, SSQ,
            p_o,      M1, HDD, HIDD,
            nullptr, SSQ);

        // manifold projection + residual (+ refresh rounded shadow)
        k_manifold<<<BB * SSQ, 256>>>(W_pinv, b_pinv,
                                      W_attn + (size_t)l * MDD * HIDD,
                                      b_attn + (size_t)l * HIDD);
    }

    // out = round(cur) @ round(W_out) + b_out   (M=8192, N=1024, K=1024)
    k_mma<<<dim3(HIDD / 128, BB * SSQ / 128, 1), 256>>>(
        p_curt, 0, 0, HIDD,
        p_wto,  0, 0, HIDD,
        out,    0, 0, HIDD,
        b_out, HIDD);
}